// round 4
// baseline (speedup 1.0000x reference)
#include <cuda_runtime.h>
#include <math.h>

#define NT 512
#define ROWS 8

typedef unsigned long long u64;

// shared memory layout (in floats)
#define OFF_H 0        // h state:   8 rows x 8 nodes x 128 = 8192 floats
#define OFF_A 8192     // hn (LN1 out)
#define OFF_B 16384    // k / attO / x-stage / mid(lo half)
#define OFF_C 24576    // v / mid(hi half)
#define OFF_D 32768    // q / att / ln2 chunk / agg
#define SMEM_FLOATS 40960

enum { EPI_STORE=0, EPI_RELU=1, EPI_GELU=2, EPI_ADD=3, EPI_RELU_ADD=4 };

__device__ __forceinline__ float gelu_f(float v) {
    return 0.5f * v * (1.0f + erff(v * 0.70710678118654752440f));
}

// ---- packed fp32x2 helpers (Blackwell FFMA2 path) ----
__device__ __forceinline__ void fma2(u64& acc, u64 a, u64 w) {
    asm("fma.rn.f32x2 %0, %1, %2, %0;" : "+l"(acc) : "l"(a), "l"(w));
}
__device__ __forceinline__ u64 pack2(float x, float y) {
    u64 r; asm("mov.b64 %0, {%1, %2};" : "=l"(r) : "f"(x), "f"(y)); return r;
}
__device__ __forceinline__ void unpack2(u64 v, float& lo, float& hi) {
    asm("mov.b64 {%0, %1}, %2;" : "=f"(lo), "=f"(hi) : "l"(v));
}

// Generic register-tiled GEMM with packed f32x2 FMAs.
// out[m][j] = act( sum_k A[m][k]*W[k][j] (+ sum A2*W) + bias[j] )
// Thread map: TJ threads along j (8 cols each, 2x ulonglong2), TM groups along m.
// TM clamped to M; threads >= TJ*TM idle. Output row offset: (m%MI)*s_in + (m/MI)*s_out.
template<int M, int K, int J, int K2, int MI, int EPI>
__device__ __forceinline__ void gemm(
    const float* __restrict__ A,  int lda,
    const float* __restrict__ A2, int lda2,
    const float* __restrict__ W,  int wld,
    const float* __restrict__ bias,
    float* __restrict__ out, int s_in, int s_out)
{
    constexpr int TJ    = (J/8 < NT) ? (J/8) : NT;
    constexpr int TMraw = NT / TJ;
    constexpr int TM    = (TMraw < M) ? TMraw : M;
    constexpr int MT    = M / TM;
    static_assert(MT * TM == M, "row mapping");

    const int t = threadIdx.x;
    if (t >= TJ * TM) return;
    const int j0 = (t % TJ) * 8;
    const int m0 = (t / TJ) * MT;

    u64 acc[MT][4];
    #pragma unroll
    for (int i = 0; i < MT; i++) { acc[i][0]=0ull; acc[i][1]=0ull; acc[i][2]=0ull; acc[i][3]=0ull; }

    #pragma unroll 2
    for (int k = 0; k < K; k += 4) {
        u64 w[4][4];
        #pragma unroll
        for (int kk = 0; kk < 4; kk++) {
            const float* Wr = W + (size_t)(k + kk) * wld + j0;
            ulonglong2 wa = *(const ulonglong2*)(Wr);
            ulonglong2 wb = *(const ulonglong2*)(Wr + 4);
            w[kk][0] = wa.x; w[kk][1] = wa.y; w[kk][2] = wb.x; w[kk][3] = wb.y;
        }
        #pragma unroll
        for (int mm = 0; mm < MT; mm++) {
            float4 a = *(const float4*)(A + (m0 + mm) * lda + k);
            u64 p0 = pack2(a.x, a.x), p1 = pack2(a.y, a.y), p2 = pack2(a.z, a.z), p3 = pack2(a.w, a.w);
            #pragma unroll
            for (int c = 0; c < 4; c++) {
                fma2(acc[mm][c], p0, w[0][c]);
                fma2(acc[mm][c], p1, w[1][c]);
                fma2(acc[mm][c], p2, w[2][c]);
                fma2(acc[mm][c], p3, w[3][c]);
            }
        }
    }
    if constexpr (K2 > 0) {
        #pragma unroll 2
        for (int k = 0; k < K2; k += 4) {
            u64 w[4][4];
            #pragma unroll
            for (int kk = 0; kk < 4; kk++) {
                const float* Wr = W + (size_t)(K + k + kk) * wld + j0;
                ulonglong2 wa = *(const ulonglong2*)(Wr);
                ulonglong2 wb = *(const ulonglong2*)(Wr + 4);
                w[kk][0] = wa.x; w[kk][1] = wa.y; w[kk][2] = wb.x; w[kk][3] = wb.y;
            }
            #pragma unroll
            for (int mm = 0; mm < MT; mm++) {
                float4 a = *(const float4*)(A2 + (m0 + mm) * lda2 + k);
                u64 p0 = pack2(a.x, a.x), p1 = pack2(a.y, a.y), p2 = pack2(a.z, a.z), p3 = pack2(a.w, a.w);
                #pragma unroll
                for (int c = 0; c < 4; c++) {
                    fma2(acc[mm][c], p0, w[0][c]);
                    fma2(acc[mm][c], p1, w[1][c]);
                    fma2(acc[mm][c], p2, w[2][c]);
                    fma2(acc[mm][c], p3, w[3][c]);
                }
            }
        }
    }

    float bs[8];
    *(float4*)(bs)     = *(const float4*)(bias + j0);
    *(float4*)(bs + 4) = *(const float4*)(bias + j0 + 4);

    #pragma unroll
    for (int mm = 0; mm < MT; mm++) {
        int m = m0 + mm;
        float* op = out + (m % MI) * s_in + (m / MI) * s_out + j0;
        float r[8];
        unpack2(acc[mm][0], r[0], r[1]);
        unpack2(acc[mm][1], r[2], r[3]);
        unpack2(acc[mm][2], r[4], r[5]);
        unpack2(acc[mm][3], r[6], r[7]);
        #pragma unroll
        for (int c = 0; c < 8; c++) {
            float v = r[c] + bs[c];
            if constexpr (EPI == EPI_STORE)    { op[c] = v; }
            if constexpr (EPI == EPI_RELU)     { op[c] = fmaxf(v, 0.f); }
            if constexpr (EPI == EPI_GELU)     { op[c] = gelu_f(v); }
            if constexpr (EPI == EPI_ADD)      { op[c] += v; }
            if constexpr (EPI == EPI_RELU_ADD) { op[c] += fmaxf(v, 0.f); }
        }
    }
}

// One LayerNorm over 128 elements: whole warp cooperates (lane owns 4 strided elems)
__device__ __forceinline__ void ln_one(const float* __restrict__ src, float* __restrict__ dst,
                                       const float* __restrict__ g, const float* __restrict__ b)
{
    const int lane = threadIdx.x & 31;
    float v0 = src[lane], v1 = src[lane+32], v2 = src[lane+64], v3 = src[lane+96];
    float s  = v0+v1+v2+v3;
    float sq = v0*v0+v1*v1+v2*v2+v3*v3;
    #pragma unroll
    for (int o = 16; o > 0; o >>= 1) {
        s  += __shfl_xor_sync(0xffffffffu, s,  o);
        sq += __shfl_xor_sync(0xffffffffu, sq, o);
    }
    float mean = s * (1.f/128.f);
    float rstd = rsqrtf(sq * (1.f/128.f) - mean*mean + 1e-5f);
    dst[lane]    = (v0-mean)*rstd*g[lane]    + b[lane];
    dst[lane+32] = (v1-mean)*rstd*g[lane+32] + b[lane+32];
    dst[lane+64] = (v2-mean)*rstd*g[lane+64] + b[lane+64];
    dst[lane+96] = (v3-mean)*rstd*g[lane+96] + b[lane+96];
}

__global__ void __launch_bounds__(NT, 1) fused_reasoner(
    const float* __restrict__ x,
    const float* __restrict__ Wp,  const float* __restrict__ bp,
    const float* __restrict__ ln1_g, const float* __restrict__ ln1_b,
    const float* __restrict__ Wq,  const float* __restrict__ bq,
    const float* __restrict__ Wk,  const float* __restrict__ bk,
    const float* __restrict__ Wv,  const float* __restrict__ bv,
    const float* __restrict__ Wo,  const float* __restrict__ bo,
    const float* __restrict__ Wu,  const float* __restrict__ bu,
    const float* __restrict__ ln2_g, const float* __restrict__ ln2_b,
    const float* __restrict__ Wf1, const float* __restrict__ bf1,
    const float* __restrict__ Wf2, const float* __restrict__ bf2,
    const float* __restrict__ Wa,  const float* __restrict__ ba,
    const float* __restrict__ Wout, const float* __restrict__ bout,
    float* __restrict__ out)
{
    extern __shared__ float S[];
    const int t = threadIdx.x;
    const int wid = t >> 5;            // 0..15
    const int row0 = blockIdx.x * ROWS;

    // ---- stage x tile (8 rows x 256) into OFF_B, then h = x @ Wp + bp ----
    {
        const float4* xg = (const float4*)(x + (size_t)row0 * 256);
        float4* xs = (float4*)(S + OFF_B);
        for (int i = t; i < 512; i += NT) xs[i] = xg[i];
    }
    __syncthreads();
    gemm<8,256,1024,0,8,EPI_STORE>(S+OFF_B,256, nullptr,0, Wp,1024, bp, S+OFF_H, 1024, 0);
    __syncthreads();

    #pragma unroll 1
    for (int l = 0; l < 3; l++) {
        const float* wq  = Wq  + l*16384;  const float* wk  = Wk  + l*16384;
        const float* wv  = Wv  + l*16384;  const float* wo  = Wo  + l*16384;
        const float* wu  = Wu  + l*32768;
        const float* wf1 = Wf1 + l*65536;  const float* wf2 = Wf2 + l*65536;
        const float* g1 = ln1_g + l*128;   const float* b1 = ln1_b + l*128;
        const float* g2 = ln2_g + l*128;   const float* b2 = ln2_b + l*128;

        // ---- LN1: hn = LN(h) over all 64 (row,node) pairs (16 warps x 4) ----
        #pragma unroll
        for (int it = 0; it < 4; it++) {
            int p = it * 16 + wid;
            ln_one(S + OFF_H + p*128, S + OFF_A + p*128, g1, b1);
        }
        __syncthreads();

        // ---- Q,K,V projections (M = 64 rows = 8 batch x 8 nodes) ----
        gemm<64,128,128,0,64,EPI_STORE>(S+OFF_A,128, nullptr,0, wq,128, bq+l*128, S+OFF_D, 128, 0);
        gemm<64,128,128,0,64,EPI_STORE>(S+OFF_A,128, nullptr,0, wk,128, bk+l*128, S+OFF_B, 128, 0);
        gemm<64,128,128,0,64,EPI_STORE>(S+OFF_A,128, nullptr,0, wv,128, bv+l*128, S+OFF_C, 128, 0);
        __syncthreads();

        // ---- causal attention: thread = (row, head, query-node); 256 of 512 threads ----
        if (t < 256) {
            const int r = t >> 5, head = (t >> 3) & 3, n = t & 7;
            const float* qp = S + OFF_D + (r*8 + n)*128 + head*32;
            float p[8];
            float mx = -1e30f;
            #pragma unroll
            for (int m = 0; m < 8; m++) {
                if (m <= n) {
                    const float* kp = S + OFF_B + (r*8 + m)*128 + head*32;
                    float s = 0.f;
                    #pragma unroll
                    for (int d = 0; d < 32; d++) s += qp[d] * kp[d];
                    s *= 0.17677669529663688f;  // 1/sqrt(32)
                    p[m] = s;
                    mx = fmaxf(mx, s);
                }
            }
            float sum = 0.f;
            #pragma unroll
            for (int m = 0; m < 8; m++) if (m <= n) { p[m] = __expf(p[m] - mx); sum += p[m]; }
            const float inv = 1.f / sum;
            float* ao = S + OFF_D + (r*8 + n)*128 + head*32;
            #pragma unroll
            for (int d = 0; d < 32; d++) {
                float o = 0.f;
                #pragma unroll
                for (int m = 0; m < 8; m++)
                    if (m <= n) o += p[m] * (S + OFF_C)[(r*8 + m)*128 + head*32 + d];
                ao[d] = o * inv;
            }
        }
        __syncthreads();

        // ---- attO = att @ Wo + bo  (into OFF_B; k is dead) ----
        gemm<64,128,128,0,64,EPI_STORE>(S+OFF_D,128, nullptr,0, wo,128, bo+l*128, S+OFF_B, 128, 0);
        __syncthreads();

        // ---- h += relu( [hn | attO] @ Wu + bu ) ----
        gemm<64,128,128,128,64,EPI_RELU_ADD>(S+OFF_A,128, S+OFF_B,128, wu,128, bu+l*128, S+OFF_H, 128, 0);
        __syncthreads();

        // ---- FFN in 2 chunks of 4 nodes (mid = 32 x 512 spans OFF_B..OFF_C) ----
        #pragma unroll 1
        for (int c = 0; c < 2; c++) {
            #pragma unroll
            for (int it = 0; it < 2; it++) {
                int p = it * 16 + wid;            // 0..31 = (r*4 + nn)
                int r = p >> 2, nn = p & 3;
                ln_one(S + OFF_H + (r*8 + c*4 + nn)*128, S + OFF_D + p*128, g2, b2);
            }
            __syncthreads();
            // mid = gelu(hn2 @ Wf1 + bf1), J=512 split into two 256-col halves
            gemm<32,128,256,0,32,EPI_GELU>(S+OFF_D,128, nullptr,0, wf1,     512, bf1+l*512,     S+OFF_B,     512, 0);
            gemm<32,128,256,0,32,EPI_GELU>(S+OFF_D,128, nullptr,0, wf1+256, 512, bf1+l*512+256, S+OFF_B+256, 512, 0);
            __syncthreads();
            // h[:, c*4+nn, :] += mid @ Wf2 + bf2   (m -> (m%4)*128 + (m/4)*1024)
            gemm<32,512,128,0,4,EPI_ADD>(S+OFF_B,512, nullptr,0, wf2,128, bf2+l*128, S+OFF_H + c*4*128, 128, 1024);
            __syncthreads();
        }
    }

    // ---- readout: agg = gelu(flat @ Wa + ba);  out = agg @ Wout + bout ----
    gemm<8,1024,128,0,8,EPI_GELU>(S+OFF_H,1024, nullptr,0, Wa,128, ba, S+OFF_D, 128, 0);
    __syncthreads();
    gemm<8,128,128,0,8,EPI_STORE>(S+OFF_D,128, nullptr,0, Wout,128, bout, out + (size_t)row0*128, 128, 0);
}

extern "C" void kernel_launch(void* const* d_in, const int* in_sizes, int n_in,
                              void* d_out, int out_size)
{
    (void)n_in; (void)out_size;
    const float* x     = (const float*)d_in[0];
    const float* Wp    = (const float*)d_in[1];
    const float* bp    = (const float*)d_in[2];
    const float* ln1_g = (const float*)d_in[3];
    const float* ln1_b = (const float*)d_in[4];
    const float* Wq    = (const float*)d_in[5];
    const float* bq    = (const float*)d_in[6];
    const float* Wk    = (const float*)d_in[7];
    const float* bk    = (const float*)d_in[8];
    const float* Wv    = (const float*)d_in[9];
    const float* bv    = (const float*)d_in[10];
    const float* Wo    = (const float*)d_in[11];
    const float* bo    = (const float*)d_in[12];
    const float* Wu    = (const float*)d_in[13];
    const float* bu    = (const float*)d_in[14];
    const float* ln2_g = (const float*)d_in[15];
    const float* ln2_b = (const float*)d_in[16];
    const float* Wf1   = (const float*)d_in[17];
    const float* bf1   = (const float*)d_in[18];
    const float* Wf2   = (const float*)d_in[19];
    const float* bf2   = (const float*)d_in[20];
    const float* Wa    = (const float*)d_in[21];
    const float* ba    = (const float*)d_in[22];
    const float* Wout  = (const float*)d_in[23];
    const float* bout  = (const float*)d_in[24];

    const int Bsz = in_sizes[0] / 256;       // DIN = 256
    const int grid = Bsz / ROWS;             // B divisible by 8
    const size_t smem = SMEM_FLOATS * sizeof(float);

    cudaFuncSetAttribute(fused_reasoner, cudaFuncAttributeMaxDynamicSharedMemorySize, (int)smem);
    fused_reasoner<<<grid, NT, smem>>>(
        x, Wp, bp, ln1_g, ln1_b, Wq, bq, Wk, bk, Wv, bv, Wo, bo,
        Wu, bu, ln2_g, ln2_b, Wf1, bf1, Wf2, bf2, Wa, ba, Wout, bout,
        (float*)d_out);
}

// round 5
// speedup vs baseline: 3.2937x; 3.2937x over previous
#include <cuda_runtime.h>
#include <math.h>

#define NT 512
#define ROWS 8
#define LDA 132            // padded row stride for 128-wide activations (132%32==4 -> conflict-free)

// shared memory layout (in floats); each main buffer holds 64 rows x LDA
#define OFF_H 0
#define OFF_A 8448
#define OFF_B 16896
#define OFF_C 25344
#define OFF_D 33792
#define SMEM_FLOATS 42240   // 168,960 bytes

enum { EPI_STORE=0, EPI_GELU=2, EPI_ADD=3, EPI_RELU_ADD=4 };

__device__ __forceinline__ float gelu_f(float v) {
    return 0.5f * v * (1.0f + erff(v * 0.70710678118654752440f));
}

// ---- tf32 mma helpers ----
__device__ __forceinline__ void mma_tf32(float* d, const unsigned* a, const unsigned* b) {
    asm("mma.sync.aligned.m16n8k8.row.col.f32.tf32.tf32.f32 "
        "{%0,%1,%2,%3}, {%4,%5,%6,%7}, {%8,%9}, {%0,%1,%2,%3};"
        : "+f"(d[0]), "+f"(d[1]), "+f"(d[2]), "+f"(d[3])
        : "r"(a[0]), "r"(a[1]), "r"(a[2]), "r"(a[3]), "r"(b[0]), "r"(b[1]));
}
// exact split: v = hi + lo, hi = truncate-to-tf32(v). HW mma ignores low 13 mantissa bits,
// so passing hi/lo raw is exact for hi and ~2^-24-accurate for lo.
__device__ __forceinline__ void split_tf32(float v, unsigned& hi, unsigned& lo) {
    unsigned h = __float_as_uint(v) & 0xFFFFE000u;
    hi = h;
    lo = __float_as_uint(v - __uint_as_float(h));
}

// Tensor-core GEMM: out[m][j] = act( sum_k A[m][k]*W[k][j] (+ sum_k2 A2[m][k2]*W[K+k2][j]) + bias[j] )
// A in smem (row-major, optional k-split addressing: elem k at (k/KI)*LDK + k%KI within row base m*lda),
// W in global (row-major K x J). Output col j -> (j/JI)*SJ + j%JI; row m -> (m%MI)*s_in + (m/MI)*s_out.
// m16n8k8 tf32 with 3-way hi/lo split (near-fp32 accuracy), fp32 accumulate.
template<int M,int K,int J,int K2,int MI,int EPI,int KI=1073741824,int LDK=0,int JI=1073741824,int SJ=0>
__device__ __forceinline__ void mma_gemm(
    const float* __restrict__ A,  int lda,
    const float* __restrict__ A2, int lda2,
    const float* __restrict__ W,  int wld,
    const float* __restrict__ bias,
    float* __restrict__ out, int s_in, int s_out)
{
    constexpr int TM16   = (M + 15) / 16;
    constexpr int TJ8    = J / 8;
    constexpr int NWARP  = NT / 32;
    static_assert((TM16 * TJ8) % NWARP == 0, "tile count must divide warps");
    constexpr int NT_S   = TM16 * TJ8 / NWARP;
    constexpr int TJSTEP = NWARP / TM16;
    constexpr bool PRED  = (M % 16) != 0;

    const int w     = threadIdx.x >> 5;
    const int lane  = threadIdx.x & 31;
    const int group = lane >> 2;
    const int tid   = lane & 3;
    const int tm    = w % TM16;
    const int tj0   = w / TM16;
    const int r0    = tm * 16 + group;
    const int r1    = r0 + 8;

    float acc[NT_S][4];
    #pragma unroll
    for (int s = 0; s < NT_S; s++) { acc[s][0]=0.f; acc[s][1]=0.f; acc[s][2]=0.f; acc[s][3]=0.f; }

    #pragma unroll 2
    for (int k8 = 0; k8 < K; k8 += 8) {
        const int ka = k8 + tid, kb = k8 + tid + 4;
        const int oa = (ka / KI) * LDK + (ka % KI);
        const int ob = (kb / KI) * LDK + (kb % KI);
        float af0, af1, af2, af3;
        if constexpr (!PRED) {
            af0 = A[r0*lda + oa]; af1 = A[r1*lda + oa];
            af2 = A[r0*lda + ob]; af3 = A[r1*lda + ob];
        } else {
            af0 = (r0 < M) ? A[r0*lda + oa] : 0.f;
            af1 = (r1 < M) ? A[r1*lda + oa] : 0.f;
            af2 = (r0 < M) ? A[r0*lda + ob] : 0.f;
            af3 = (r1 < M) ? A[r1*lda + ob] : 0.f;
        }
        unsigned ah[4], al[4];
        split_tf32(af0, ah[0], al[0]); split_tf32(af1, ah[1], al[1]);
        split_tf32(af2, ah[2], al[2]); split_tf32(af3, ah[3], al[3]);
        #pragma unroll
        for (int s = 0; s < NT_S; s++) {
            const int j0 = (tj0 + s * TJSTEP) * 8;
            float bf0 = W[ka * wld + j0 + group];
            float bf1 = W[kb * wld + j0 + group];
            unsigned bh[2], bl[2];
            split_tf32(bf0, bh[0], bl[0]);
            split_tf32(bf1, bh[1], bl[1]);
            mma_tf32(acc[s], ah, bh);
            mma_tf32(acc[s], ah, bl);
            mma_tf32(acc[s], al, bh);
        }
    }
    if constexpr (K2 > 0) {
        #pragma unroll 2
        for (int k8 = 0; k8 < K2; k8 += 8) {
            const int ka = k8 + tid, kb = k8 + tid + 4;
            float af0 = A2[r0*lda2 + ka], af1 = A2[r1*lda2 + ka];
            float af2 = A2[r0*lda2 + kb], af3 = A2[r1*lda2 + kb];
            unsigned ah[4], al[4];
            split_tf32(af0, ah[0], al[0]); split_tf32(af1, ah[1], al[1]);
            split_tf32(af2, ah[2], al[2]); split_tf32(af3, ah[3], al[3]);
            #pragma unroll
            for (int s = 0; s < NT_S; s++) {
                const int j0 = (tj0 + s * TJSTEP) * 8;
                float bf0 = W[(K + ka) * wld + j0 + group];
                float bf1 = W[(K + kb) * wld + j0 + group];
                unsigned bh[2], bl[2];
                split_tf32(bf0, bh[0], bl[0]);
                split_tf32(bf1, bh[1], bl[1]);
                mma_tf32(acc[s], ah, bh);
                mma_tf32(acc[s], ah, bl);
                mma_tf32(acc[s], al, bh);
            }
        }
    }

    // epilogue
    #pragma unroll
    for (int s = 0; s < NT_S; s++) {
        const int j0 = (tj0 + s * TJSTEP) * 8;
        const int c0 = j0 + 2 * tid;
        const float b0 = bias[c0], b1 = bias[c0 + 1];
        const int jo = (c0 / JI) * SJ + (c0 % JI);
        float v00 = acc[s][0] + b0, v01 = acc[s][1] + b1;
        float v10 = acc[s][2] + b0, v11 = acc[s][3] + b1;
        if (!PRED || r0 < M) {
            float* p = out + (r0 % MI) * s_in + (r0 / MI) * s_out + jo;
            if constexpr (EPI == EPI_STORE)    { p[0] = v00;                    p[1] = v01; }
            if constexpr (EPI == EPI_GELU)     { p[0] = gelu_f(v00);            p[1] = gelu_f(v01); }
            if constexpr (EPI == EPI_ADD)      { p[0] += v00;                   p[1] += v01; }
            if constexpr (EPI == EPI_RELU_ADD) { p[0] += fmaxf(v00, 0.f);       p[1] += fmaxf(v01, 0.f); }
        }
        if (!PRED || r1 < M) {
            float* p = out + (r1 % MI) * s_in + (r1 / MI) * s_out + jo;
            if constexpr (EPI == EPI_STORE)    { p[0] = v10;                    p[1] = v11; }
            if constexpr (EPI == EPI_GELU)     { p[0] = gelu_f(v10);            p[1] = gelu_f(v11); }
            if constexpr (EPI == EPI_ADD)      { p[0] += v10;                   p[1] += v11; }
            if constexpr (EPI == EPI_RELU_ADD) { p[0] += fmaxf(v10, 0.f);       p[1] += fmaxf(v11, 0.f); }
        }
    }
}

// One LayerNorm over 128 elements: whole warp cooperates (lane owns 4 strided elems)
__device__ __forceinline__ void ln_one(const float* __restrict__ src, float* __restrict__ dst,
                                       const float* __restrict__ g, const float* __restrict__ b)
{
    const int lane = threadIdx.x & 31;
    float v0 = src[lane], v1 = src[lane+32], v2 = src[lane+64], v3 = src[lane+96];
    float s  = v0+v1+v2+v3;
    float sq = v0*v0+v1*v1+v2*v2+v3*v3;
    #pragma unroll
    for (int o = 16; o > 0; o >>= 1) {
        s  += __shfl_xor_sync(0xffffffffu, s,  o);
        sq += __shfl_xor_sync(0xffffffffu, sq, o);
    }
    float mean = s * (1.f/128.f);
    float rstd = rsqrtf(sq * (1.f/128.f) - mean*mean + 1e-5f);
    dst[lane]    = (v0-mean)*rstd*g[lane]    + b[lane];
    dst[lane+32] = (v1-mean)*rstd*g[lane+32] + b[lane+32];
    dst[lane+64] = (v2-mean)*rstd*g[lane+64] + b[lane+64];
    dst[lane+96] = (v3-mean)*rstd*g[lane+96] + b[lane+96];
}

__global__ void __launch_bounds__(NT, 1) fused_reasoner(
    const float* __restrict__ x,
    const float* __restrict__ Wp,  const float* __restrict__ bp,
    const float* __restrict__ ln1_g, const float* __restrict__ ln1_b,
    const float* __restrict__ Wq,  const float* __restrict__ bq,
    const float* __restrict__ Wk,  const float* __restrict__ bk,
    const float* __restrict__ Wv,  const float* __restrict__ bv,
    const float* __restrict__ Wo,  const float* __restrict__ bo,
    const float* __restrict__ Wu,  const float* __restrict__ bu,
    const float* __restrict__ ln2_g, const float* __restrict__ ln2_b,
    const float* __restrict__ Wf1, const float* __restrict__ bf1,
    const float* __restrict__ Wf2, const float* __restrict__ bf2,
    const float* __restrict__ Wa,  const float* __restrict__ ba,
    const float* __restrict__ Wout, const float* __restrict__ bout,
    float* __restrict__ out)
{
    extern __shared__ float S[];
    const int t = threadIdx.x;
    const int wid = t >> 5;            // 0..15
    const int row0 = blockIdx.x * ROWS;

    // ---- stage x tile (8 rows x 256, padded lda=260) into OFF_B ----
    {
        const float4* xg = (const float4*)(x + (size_t)row0 * 256);
        for (int i = t; i < 512; i += NT) {
            int r = i >> 6, c4 = i & 63;               // 64 float4 per row
            *(float4*)(S + OFF_B + r*260 + c4*4) = xg[r*64 + c4];
        }
    }
    __syncthreads();
    // h = x @ Wp + bp : out col j -> H row r*8 + j/128, col j%128
    mma_gemm<8,256,1024,0,8,EPI_STORE, 1073741824,0, 128,LDA>(
        S+OFF_B,260, nullptr,0, Wp,1024, bp, S+OFF_H, 8*LDA, 0);
    __syncthreads();

    #pragma unroll 1
    for (int l = 0; l < 3; l++) {
        const float* wq  = Wq  + l*16384;  const float* wk  = Wk  + l*16384;
        const float* wv  = Wv  + l*16384;  const float* wo  = Wo  + l*16384;
        const float* wu  = Wu  + l*32768;
        const float* wf1 = Wf1 + l*65536;  const float* wf2 = Wf2 + l*65536;
        const float* g1 = ln1_g + l*128;   const float* b1 = ln1_b + l*128;
        const float* g2 = ln2_g + l*128;   const float* b2 = ln2_b + l*128;

        // ---- LN1: 64 (row,node) pairs, 16 warps x 4 ----
        #pragma unroll
        for (int it = 0; it < 4; it++) {
            int p = it * 16 + wid;
            ln_one(S + OFF_H + p*LDA, S + OFF_A + p*LDA, g1, b1);
        }
        __syncthreads();

        // ---- Q,K,V projections ----
        mma_gemm<64,128,128,0,64,EPI_STORE>(S+OFF_A,LDA, nullptr,0, wq,128, bq+l*128, S+OFF_D, LDA, 0);
        mma_gemm<64,128,128,0,64,EPI_STORE>(S+OFF_A,LDA, nullptr,0, wk,128, bk+l*128, S+OFF_B, LDA, 0);
        mma_gemm<64,128,128,0,64,EPI_STORE>(S+OFF_A,LDA, nullptr,0, wv,128, bv+l*128, S+OFF_C, LDA, 0);
        __syncthreads();

        // ---- causal attention: thread = (row, head, query-node); 256 of 512 threads ----
        if (t < 256) {
            const int r = t >> 5, head = (t >> 3) & 3, n = t & 7;
            const float* qp = S + OFF_D + (r*8 + n)*LDA + head*32;
            float p[8];
            float mx = -1e30f;
            #pragma unroll
            for (int m = 0; m < 8; m++) {
                if (m <= n) {
                    const float* kp = S + OFF_B + (r*8 + m)*LDA + head*32;
                    float s = 0.f;
                    #pragma unroll
                    for (int d = 0; d < 32; d++) s += qp[d] * kp[d];
                    s *= 0.17677669529663688f;  // 1/sqrt(32)
                    p[m] = s;
                    mx = fmaxf(mx, s);
                }
            }
            float sum = 0.f;
            #pragma unroll
            for (int m = 0; m < 8; m++) if (m <= n) { p[m] = __expf(p[m] - mx); sum += p[m]; }
            const float inv = 1.f / sum;
            float* ao = S + OFF_D + (r*8 + n)*LDA + head*32;
            #pragma unroll
            for (int d = 0; d < 32; d++) {
                float o = 0.f;
                #pragma unroll
                for (int m = 0; m < 8; m++)
                    if (m <= n) o += p[m] * (S + OFF_C)[(r*8 + m)*LDA + head*32 + d];
                ao[d] = o * inv;
            }
        }
        __syncthreads();

        // ---- attO = att @ Wo + bo  (into OFF_B; k dead) ----
        mma_gemm<64,128,128,0,64,EPI_STORE>(S+OFF_D,LDA, nullptr,0, wo,128, bo+l*128, S+OFF_B, LDA, 0);
        __syncthreads();

        // ---- h += relu( [hn | attO] @ Wu + bu ) ----
        mma_gemm<64,128,128,128,64,EPI_RELU_ADD>(S+OFF_A,LDA, S+OFF_B,LDA, wu,128, bu+l*128, S+OFF_H, LDA, 0);
        __syncthreads();

        // ---- FFN in 2 chunks of 4 nodes (mid = 32 x 512, lda=516, spans OFF_B..OFF_C) ----
        #pragma unroll 1
        for (int c = 0; c < 2; c++) {
            #pragma unroll
            for (int it = 0; it < 2; it++) {
                int p = it * 16 + wid;            // 0..31 = (r*4 + nn)
                int r = p >> 2, nn = p & 3;
                ln_one(S + OFF_H + (r*8 + c*4 + nn)*LDA, S + OFF_D + p*LDA, g2, b2);
            }
            __syncthreads();
            // mid = gelu(hn2 @ Wf1 + bf1)
            mma_gemm<32,128,512,0,32,EPI_GELU>(S+OFF_D,LDA, nullptr,0, wf1,512, bf1+l*512, S+OFF_B, 516, 0);
            __syncthreads();
            // h[:, c*4+nn, :] += mid @ Wf2 + bf2  (row m -> (m%4)*LDA + (m/4)*8*LDA)
            mma_gemm<32,512,128,0,4,EPI_ADD>(S+OFF_B,516, nullptr,0, wf2,128, bf2+l*128,
                                             S+OFF_H + c*4*LDA, LDA, 8*LDA);
            __syncthreads();
        }
    }

    // ---- readout: agg = gelu(flat @ Wa + ba)  (flat k -> H row m*8 + k/128, col k%128) ----
    mma_gemm<8,1024,128,0,8,EPI_GELU, 128,LDA>(S+OFF_H, 8*LDA, nullptr,0, Wa,128, ba, S+OFF_D, LDA, 0);
    __syncthreads();
    // out = agg @ Wout + bout  (global, unpadded stride 128)
    mma_gemm<8,128,128,0,8,EPI_STORE>(S+OFF_D,LDA, nullptr,0, Wout,128, bout, out + (size_t)row0*128, 128, 0);
}

extern "C" void kernel_launch(void* const* d_in, const int* in_sizes, int n_in,
                              void* d_out, int out_size)
{
    (void)n_in; (void)out_size;
    const float* x     = (const float*)d_in[0];
    const float* Wp    = (const float*)d_in[1];
    const float* bp    = (const float*)d_in[2];
    const float* ln1_g = (const float*)d_in[3];
    const float* ln1_b = (const float*)d_in[4];
    const float* Wq    = (const float*)d_in[5];
    const float* bq    = (const float*)d_in[6];
    const float* Wk    = (const float*)d_in[7];
    const float* bk    = (const float*)d_in[8];
    const float* Wv    = (const float*)d_in[9];
    const float* bv    = (const float*)d_in[10];
    const float* Wo    = (const float*)d_in[11];
    const float* bo    = (const float*)d_in[12];
    const float* Wu    = (const float*)d_in[13];
    const float* bu    = (const float*)d_in[14];
    const float* ln2_g = (const float*)d_in[15];
    const float* ln2_b = (const float*)d_in[16];
    const float* Wf1   = (const float*)d_in[17];
    const float* bf1   = (const float*)d_in[18];
    const float* Wf2   = (const float*)d_in[19];
    const float* bf2   = (const float*)d_in[20];
    const float* Wa    = (const float*)d_in[21];
    const float* ba    = (const float*)d_in[22];
    const float* Wout  = (const float*)d_in[23];
    const float* bout  = (const float*)d_in[24];

    const int Bsz = in_sizes[0] / 256;       // DIN = 256
    const int grid = Bsz / ROWS;             // B divisible by 8
    const size_t smem = SMEM_FLOATS * sizeof(float);

    cudaFuncSetAttribute(fused_reasoner, cudaFuncAttributeMaxDynamicSharedMemorySize, (int)smem);
    fused_reasoner<<<grid, NT, smem>>>(
        x, Wp, bp, ln1_g, ln1_b, Wq, bq, Wk, bk, Wv, bv, Wo, bo,
        Wu, bu, ln2_g, ln2_b, Wf1, bf1, Wf2, bf2, Wa, ba, Wout, bout,
        (float*)d_out);
}

// round 7
// speedup vs baseline: 3.5258x; 1.0705x over previous
#include <cuda_runtime.h>
#include <math.h>

#define NT 512
#define ROWS 8
#define LDA 132            // padded row stride for 128-wide activations (132%32==4 -> conflict-free)

// shared memory layout (in floats); each main buffer holds 64 rows x LDA
#define OFF_H 0
#define OFF_A 8448
#define OFF_B 16896
#define OFF_C 25344
#define OFF_D 33792
#define SMEM_FLOATS 42240   // 168,960 bytes

// ---- packed (pre-split) weight scratch: uint4{bh0,bl0,bh1,bl1} per [k8][jt][lane] ----
#define PK_WP     0
#define PK_L0     131072
#define PK_LSTR   114688
#define PK_WQ     0
#define PK_WK     8192
#define PK_WV     16384
#define PK_WO     24576
#define PK_WU     32768
#define PK_WF1    49152
#define PK_WF2    81920
#define PK_WA     475136
#define PK_WOUT   540672
#define PK_TOTAL  548864

__device__ uint4 g_packed[PK_TOTAL];

enum { EPI_STORE=0, EPI_GELU=2, EPI_ADD=3, EPI_RELU_ADD=4 };

__device__ __forceinline__ float gelu_f(float v) {
    return 0.5f * v * (1.0f + erff(v * 0.70710678118654752440f));
}

// ---- tf32 mma helpers ----
__device__ __forceinline__ void mma_tf32(float* d, const unsigned* a, const unsigned* b) {
    asm("mma.sync.aligned.m16n8k8.row.col.f32.tf32.tf32.f32 "
        "{%0,%1,%2,%3}, {%4,%5,%6,%7}, {%8,%9}, {%0,%1,%2,%3};"
        : "+f"(d[0]), "+f"(d[1]), "+f"(d[2]), "+f"(d[3])
        : "r"(a[0]), "r"(a[1]), "r"(a[2]), "r"(a[3]), "r"(b[0]), "r"(b[1]));
}
// exact split: v = hi + lo, hi = truncate-to-tf32(v).
__device__ __forceinline__ void split_tf32(float v, unsigned& hi, unsigned& lo) {
    unsigned h = __float_as_uint(v) & 0xFFFFE000u;
    hi = h;
    lo = __float_as_uint(v - __uint_as_float(h));
}

// ---- weight pre-splitter: W (K x J row-major) -> fragment-order packed uint4 ----
__global__ void pack_weights(const float* __restrict__ Wp, const float* __restrict__ Wq,
        const float* __restrict__ Wk, const float* __restrict__ Wv, const float* __restrict__ Wo,
        const float* __restrict__ Wu, const float* __restrict__ Wf1, const float* __restrict__ Wf2,
        const float* __restrict__ Wa, const float* __restrict__ Wout)
{
    const float* src[24]; int Js[24]; long base[24]; int ents[24];
    int n = 0; long off = 0;
    #define ADDSEG(w, K_, J_) { src[n]=(w); Js[n]=(J_); ents[n]=(K_)*(J_)/2; base[n]=off; off+=(K_)*(J_)/2; n++; }
    ADDSEG(Wp, 256, 1024);
    for (int l = 0; l < 3; l++) {
        ADDSEG(Wq+l*16384,128,128); ADDSEG(Wk+l*16384,128,128); ADDSEG(Wv+l*16384,128,128);
        ADDSEG(Wo+l*16384,128,128); ADDSEG(Wu+l*32768,256,128);
        ADDSEG(Wf1+l*65536,128,512); ADDSEG(Wf2+l*65536,512,128);
    }
    ADDSEG(Wa,1024,128); ADDSEG(Wout,128,128);
    #undef ADDSEG
    // n == 24 segments total

    for (long idx = blockIdx.x*(long)blockDim.x + threadIdx.x; idx < PK_TOTAL;
         idx += (long)gridDim.x * blockDim.x) {
        int s = 0;
        while (s < 23 && idx >= base[s] + ents[s]) s++;
        long e = idx - base[s];
        const float* W = src[s]; const int J = Js[s];
        int lane = (int)(e & 31);
        long tmp = e >> 5;
        int jt = (int)(tmp % (J/8));
        int k8 = (int)(tmp / (J/8));
        int tid = lane & 3, group = lane >> 2;
        int ka = k8*8 + tid, j = jt*8 + group;
        float v0 = W[(size_t)ka*J + j];
        float v1 = W[(size_t)(ka+4)*J + j];
        unsigned h0,l0,h1,l1;
        split_tf32(v0,h0,l0); split_tf32(v1,h1,l1);
        g_packed[idx] = make_uint4(h0,l0,h1,l1);
    }
}

// Tensor-core GEMM on pre-split packed weights.
// out[m][j] = act( sum_k A[m][k]*W[k][j] (+ sum_k2 A2[m][k2]*W[K+k2][j]) + bias[j] )
// A in smem (row-major; optional k-split addressing: elem k at (k/KI)*LDK + k%KI).
// Output col j -> (j/JI)*SJ + j%JI; row m -> (m%MI)*s_in + (m/MI)*s_out.
template<int M,int K,int J,int K2,int MI,int EPI,int KI=1073741824,int LDK=0,int JI=1073741824,int SJ=0>
__device__ __forceinline__ void mma_gemm(
    const float* __restrict__ A,  int lda,
    const float* __restrict__ A2, int lda2,
    const uint4* __restrict__ Wpk,
    const float* __restrict__ bias,
    float* __restrict__ out, int s_in, int s_out)
{
    constexpr int TM16   = (M + 15) / 16;
    constexpr int TJ8    = J / 8;
    constexpr int NWARP  = NT / 32;
    static_assert((TM16 * TJ8) % NWARP == 0, "tile count must divide warps");
    constexpr int NT_S   = TM16 * TJ8 / NWARP;
    constexpr int TJSTEP = NWARP / TM16;
    constexpr bool PRED  = (M % 16) != 0;

    const int w     = threadIdx.x >> 5;
    const int lane  = threadIdx.x & 31;
    const int group = lane >> 2;
    const int tid   = lane & 3;
    const int tm    = w % TM16;
    const int tj0   = w / TM16;
    const int r0    = tm * 16 + group;
    const int r1    = r0 + 8;

    float acc[NT_S][4];
    #pragma unroll
    for (int s = 0; s < NT_S; s++) { acc[s][0]=0.f; acc[s][1]=0.f; acc[s][2]=0.f; acc[s][3]=0.f; }

    #pragma unroll 2
    for (int k8 = 0; k8 < K; k8 += 8) {
        const int kk = k8 >> 3;
        const int ka = k8 + tid, kb = k8 + tid + 4;
        const int oa = (ka / KI) * LDK + (ka % KI);
        const int ob = (kb / KI) * LDK + (kb % KI);
        float af0, af1, af2, af3;
        if constexpr (!PRED) {
            af0 = A[r0*lda + oa]; af1 = A[r1*lda + oa];
            af2 = A[r0*lda + ob]; af3 = A[r1*lda + ob];
        } else {
            af0 = (r0 < M) ? A[r0*lda + oa] : 0.f;
            af1 = (r1 < M) ? A[r1*lda + oa] : 0.f;
            af2 = (r0 < M) ? A[r0*lda + ob] : 0.f;
            af3 = (r1 < M) ? A[r1*lda + ob] : 0.f;
        }
        unsigned ah[4], al[4];
        split_tf32(af0, ah[0], al[0]); split_tf32(af1, ah[1], al[1]);
        split_tf32(af2, ah[2], al[2]); split_tf32(af3, ah[3], al[3]);
        #pragma unroll
        for (int s = 0; s < NT_S; s++) {
            uint4 b = Wpk[((long)kk * TJ8 + tj0 + s * TJSTEP) * 32 + lane];
            unsigned bh[2] = {b.x, b.z}, bl[2] = {b.y, b.w};
            mma_tf32(acc[s], ah, bh);
            mma_tf32(acc[s], ah, bl);
            mma_tf32(acc[s], al, bh);
        }
    }
    if constexpr (K2 > 0) {
        #pragma unroll 2
        for (int k8 = 0; k8 < K2; k8 += 8) {
            const int kk = (K + k8) >> 3;
            const int ka = k8 + tid, kb = k8 + tid + 4;
            float af0 = A2[r0*lda2 + ka], af1 = A2[r1*lda2 + ka];
            float af2 = A2[r0*lda2 + kb], af3 = A2[r1*lda2 + kb];
            unsigned ah[4], al[4];
            split_tf32(af0, ah[0], al[0]); split_tf32(af1, ah[1], al[1]);
            split_tf32(af2, ah[2], al[2]); split_tf32(af3, ah[3], al[3]);
            #pragma unroll
            for (int s = 0; s < NT_S; s++) {
                uint4 b = Wpk[((long)kk * TJ8 + tj0 + s * TJSTEP) * 32 + lane];
                unsigned bh[2] = {b.x, b.z}, bl[2] = {b.y, b.w};
                mma_tf32(acc[s], ah, bh);
                mma_tf32(acc[s], ah, bl);
                mma_tf32(acc[s], al, bh);
            }
        }
    }

    // epilogue
    #pragma unroll
    for (int s = 0; s < NT_S; s++) {
        const int j0 = (tj0 + s * TJSTEP) * 8;
        const int c0 = j0 + 2 * tid;
        const float b0 = bias[c0], b1 = bias[c0 + 1];
        const int jo = (c0 / JI) * SJ + (c0 % JI);
        float v00 = acc[s][0] + b0, v01 = acc[s][1] + b1;
        float v10 = acc[s][2] + b0, v11 = acc[s][3] + b1;
        if (!PRED || r0 < M) {
            float* p = out + (r0 % MI) * s_in + (r0 / MI) * s_out + jo;
            if constexpr (EPI == EPI_STORE)    { p[0] = v00;              p[1] = v01; }
            if constexpr (EPI == EPI_GELU)     { p[0] = gelu_f(v00);      p[1] = gelu_f(v01); }
            if constexpr (EPI == EPI_ADD)      { p[0] += v00;             p[1] += v01; }
            if constexpr (EPI == EPI_RELU_ADD) { p[0] += fmaxf(v00, 0.f); p[1] += fmaxf(v01, 0.f); }
        }
        if (!PRED || r1 < M) {
            float* p = out + (r1 % MI) * s_in + (r1 / MI) * s_out + jo;
            if constexpr (EPI == EPI_STORE)    { p[0] = v10;              p[1] = v11; }
            if constexpr (EPI == EPI_GELU)     { p[0] = gelu_f(v10);      p[1] = gelu_f(v11); }
            if constexpr (EPI == EPI_ADD)      { p[0] += v10;             p[1] += v11; }
            if constexpr (EPI == EPI_RELU_ADD) { p[0] += fmaxf(v10, 0.f); p[1] += fmaxf(v11, 0.f); }
        }
    }
}

// One LayerNorm over 128 elements: whole warp cooperates (lane owns 4 strided elems)
__device__ __forceinline__ void ln_one(const float* __restrict__ src, float* __restrict__ dst,
                                       const float* __restrict__ g, const float* __restrict__ b)
{
    const int lane = threadIdx.x & 31;
    float v0 = src[lane], v1 = src[lane+32], v2 = src[lane+64], v3 = src[lane+96];
    float s  = v0+v1+v2+v3;
    float sq = v0*v0+v1*v1+v2*v2+v3*v3;
    #pragma unroll
    for (int o = 16; o > 0; o >>= 1) {
        s  += __shfl_xor_sync(0xffffffffu, s,  o);
        sq += __shfl_xor_sync(0xffffffffu, sq, o);
    }
    float mean = s * (1.f/128.f);
    float rstd = rsqrtf(sq * (1.f/128.f) - mean*mean + 1e-5f);
    dst[lane]    = (v0-mean)*rstd*g[lane]    + b[lane];
    dst[lane+32] = (v1-mean)*rstd*g[lane+32] + b[lane+32];
    dst[lane+64] = (v2-mean)*rstd*g[lane+64] + b[lane+64];
    dst[lane+96] = (v3-mean)*rstd*g[lane+96] + b[lane+96];
}

__global__ void __launch_bounds__(NT, 1) fused_reasoner(
    const float* __restrict__ x,
    const float* __restrict__ bp,
    const float* __restrict__ ln1_g, const float* __restrict__ ln1_b,
    const float* __restrict__ bq, const float* __restrict__ bk,
    const float* __restrict__ bv, const float* __restrict__ bo,
    const float* __restrict__ bu,
    const float* __restrict__ ln2_g, const float* __restrict__ ln2_b,
    const float* __restrict__ bf1, const float* __restrict__ bf2,
    const float* __restrict__ ba, const float* __restrict__ bout,
    float* __restrict__ out)
{
    extern __shared__ float S[];
    const int t = threadIdx.x;
    const int wid = t >> 5;            // 0..15
    const int row0 = blockIdx.x * ROWS;

    // ---- stage x tile (8 rows x 256, padded lda=260) into OFF_B ----
    {
        const float4* xg = (const float4*)(x + (size_t)row0 * 256);
        for (int i = t; i < 512; i += NT) {
            int r = i >> 6, c4 = i & 63;               // 64 float4 per row
            *(float4*)(S + OFF_B + r*260 + c4*4) = xg[r*64 + c4];
        }
    }
    __syncthreads();
    // h = x @ Wp + bp : out col j -> H row r*8 + j/128, col j%128
    mma_gemm<8,256,1024,0,8,EPI_STORE, 1073741824,0, 128,LDA>(
        S+OFF_B,260, nullptr,0, g_packed+PK_WP, bp, S+OFF_H, 8*LDA, 0);
    __syncthreads();

    #pragma unroll 1
    for (int l = 0; l < 3; l++) {
        const uint4* pkl = g_packed + PK_L0 + (long)l * PK_LSTR;
        const float* g1 = ln1_g + l*128;   const float* b1 = ln1_b + l*128;
        const float* g2 = ln2_g + l*128;   const float* b2 = ln2_b + l*128;

        // ---- LN1: 64 (row,node) pairs, 16 warps x 4 ----
        #pragma unroll
        for (int it = 0; it < 4; it++) {
            int p = it * 16 + wid;
            ln_one(S + OFF_H + p*LDA, S + OFF_A + p*LDA, g1, b1);
        }
        __syncthreads();

        // ---- Q,K,V projections ----
        mma_gemm<64,128,128,0,64,EPI_STORE>(S+OFF_A,LDA, nullptr,0, pkl+PK_WQ, bq+l*128, S+OFF_D, LDA, 0);
        mma_gemm<64,128,128,0,64,EPI_STORE>(S+OFF_A,LDA, nullptr,0, pkl+PK_WK, bk+l*128, S+OFF_B, LDA, 0);
        mma_gemm<64,128,128,0,64,EPI_STORE>(S+OFF_A,LDA, nullptr,0, pkl+PK_WV, bv+l*128, S+OFF_C, LDA, 0);
        __syncthreads();

        // ---- causal attention: thread = (row, head, query-node); 256 of 512 threads ----
        if (t < 256) {
            const int r = t >> 5, head = (t >> 3) & 3, n = t & 7;
            const float* qp = S + OFF_D + (r*8 + n)*LDA + head*32;
            float p[8];
            float mx = -1e30f;
            #pragma unroll
            for (int m = 0; m < 8; m++) {
                if (m <= n) {
                    const float* kp = S + OFF_B + (r*8 + m)*LDA + head*32;
                    float s = 0.f;
                    #pragma unroll
                    for (int d = 0; d < 32; d++) s += qp[d] * kp[d];
                    s *= 0.17677669529663688f;  // 1/sqrt(32)
                    p[m] = s;
                    mx = fmaxf(mx, s);
                }
            }
            float sum = 0.f;
            #pragma unroll
            for (int m = 0; m < 8; m++) if (m <= n) { p[m] = __expf(p[m] - mx); sum += p[m]; }
            const float inv = 1.f / sum;
            float* ao = S + OFF_D + (r*8 + n)*LDA + head*32;
            #pragma unroll
            for (int d = 0; d < 32; d++) {
                float o = 0.f;
                #pragma unroll
                for (int m = 0; m < 8; m++)
                    if (m <= n) o += p[m] * (S + OFF_C)[(r*8 + m)*LDA + head*32 + d];
                ao[d] = o * inv;
            }
        }
        __syncthreads();

        // ---- attO = att @ Wo + bo  (into OFF_B; k dead) ----
        mma_gemm<64,128,128,0,64,EPI_STORE>(S+OFF_D,LDA, nullptr,0, pkl+PK_WO, bo+l*128, S+OFF_B, LDA, 0);
        __syncthreads();

        // ---- h += relu( [hn | attO] @ Wu + bu ) ----
        mma_gemm<64,128,128,128,64,EPI_RELU_ADD>(S+OFF_A,LDA, S+OFF_B,LDA, pkl+PK_WU, bu+l*128, S+OFF_H, LDA, 0);
        __syncthreads();

        // ---- FFN in 2 chunks of 4 nodes (mid = 32 x 512, lda=516, spans OFF_B..OFF_C) ----
        #pragma unroll 1
        for (int c = 0; c < 2; c++) {
            #pragma unroll
            for (int it = 0; it < 2; it++) {
                int p = it * 16 + wid;            // 0..31 = (r*4 + nn)
                int r = p >> 2, nn = p & 3;
                ln_one(S + OFF_H + (r*8 + c*4 + nn)*LDA, S + OFF_D + p*LDA, g2, b2);
            }
            __syncthreads();
            // mid = gelu(hn2 @ Wf1 + bf1)
            mma_gemm<32,128,512,0,32,EPI_GELU>(S+OFF_D,LDA, nullptr,0, pkl+PK_WF1, bf1+l*512, S+OFF_B, 516, 0);
            __syncthreads();
            // h[:, c*4+nn, :] += mid @ Wf2 + bf2  (row m -> (m%4)*LDA + (m/4)*8*LDA)
            mma_gemm<32,512,128,0,4,EPI_ADD>(S+OFF_B,516, nullptr,0, pkl+PK_WF2, bf2+l*128,
                                             S+OFF_H + c*4*LDA, LDA, 8*LDA);
            __syncthreads();
        }
    }

    // ---- readout: agg = gelu(flat @ Wa + ba)  (flat k -> H row m*8 + k/128, col k%128) ----
    mma_gemm<8,1024,128,0,8,EPI_GELU, 128,LDA>(S+OFF_H, 8*LDA, nullptr,0, g_packed+PK_WA, ba, S+OFF_D, LDA, 0);
    __syncthreads();
    // out = agg @ Wout + bout  (global, unpadded stride 128)
    mma_gemm<8,128,128,0,8,EPI_STORE>(S+OFF_D,LDA, nullptr,0, g_packed+PK_WOUT, bout,
                                      out + (size_t)row0*128, 128, 0);
}

extern "C" void kernel_launch(void* const* d_in, const int* in_sizes, int n_in,
                              void* d_out, int out_size)
{
    (void)n_in; (void)out_size;
    const float* x     = (const float*)d_in[0];
    const float* Wp    = (const float*)d_in[1];
    const float* bp    = (const float*)d_in[2];
    const float* ln1_g = (const float*)d_in[3];
    const float* ln1_b = (const float*)d_in[4];
    const float* Wq    = (const float*)d_in[5];
    const float* bq    = (const float*)d_in[6];
    const float* Wk    = (const float*)d_in[7];
    const float* bk    = (const float*)d_in[8];
    const float* Wv    = (const float*)d_in[9];
    const float* bv    = (const float*)d_in[10];
    const float* Wo    = (const float*)d_in[11];
    const float* bo    = (const float*)d_in[12];
    const float* Wu    = (const float*)d_in[13];
    const float* bu    = (const float*)d_in[14];
    const float* ln2_g = (const float*)d_in[15];
    const float* ln2_b = (const float*)d_in[16];
    const float* Wf1   = (const float*)d_in[17];
    const float* bf1   = (const float*)d_in[18];
    const float* Wf2   = (const float*)d_in[19];
    const float* bf2   = (const float*)d_in[20];
    const float* Wa    = (const float*)d_in[21];
    const float* ba    = (const float*)d_in[22];
    const float* Wout  = (const float*)d_in[23];
    const float* bout  = (const float*)d_in[24];

    const int Bsz = in_sizes[0] / 256;       // DIN = 256
    const int grid = Bsz / ROWS;             // B divisible by 8
    const size_t smem = SMEM_FLOATS * sizeof(float);

    pack_weights<<<2144, 256>>>(Wp, Wq, Wk, Wv, Wo, Wu, Wf1, Wf2, Wa, Wout);

    cudaFuncSetAttribute(fused_reasoner, cudaFuncAttributeMaxDynamicSharedMemorySize, (int)smem);
    fused_reasoner<<<grid, NT, smem>>>(
        x, bp, ln1_g, ln1_b, bq, bk, bv, bo, bu, ln2_g, ln2_b,
        bf1, bf2, ba, bout, (float*)d_out);
}

// round 8
// speedup vs baseline: 3.7770x; 1.0713x over previous
#include <cuda_runtime.h>
#include <math.h>

#define NT 512
#define ROWS 8
#define LDA 132            // padded row stride for 128-wide activations (132%32==4 -> conflict-free)

// shared memory layout (in floats); each main buffer holds 64 rows x LDA
#define OFF_H 0
#define OFF_A 8448
#define OFF_B 16896
#define OFF_C 25344
#define OFF_D 33792
#define SMEM_FLOATS 42240   // 168,960 bytes

// ---- packed (pre-split) weight scratch: uint4{bh0,bl0,bh1,bl1} per [k8][jt][lane] ----
#define PK_WP     0
#define PK_L0     131072
#define PK_LSTR   114688
#define PK_WQ     0
#define PK_WK     8192
#define PK_WV     16384
#define PK_WO     24576
#define PK_WU     32768
#define PK_WF1    49152
#define PK_WF2    81920
#define PK_WA     475136
#define PK_WOUT   540672
#define PK_TOTAL  548864

__device__ uint4 g_packed[PK_TOTAL];

enum { EPI_STORE=0, EPI_GELU=2, EPI_ADD=3, EPI_RELU_ADD=4 };

__device__ __forceinline__ float gelu_f(float v) {
    return 0.5f * v * (1.0f + erff(v * 0.70710678118654752440f));
}

// ---- tf32 mma helpers ----
__device__ __forceinline__ void mma_tf32(float* d, const unsigned* a, const unsigned* b) {
    asm("mma.sync.aligned.m16n8k8.row.col.f32.tf32.tf32.f32 "
        "{%0,%1,%2,%3}, {%4,%5,%6,%7}, {%8,%9}, {%0,%1,%2,%3};"
        : "+f"(d[0]), "+f"(d[1]), "+f"(d[2]), "+f"(d[3])
        : "r"(a[0]), "r"(a[1]), "r"(a[2]), "r"(a[3]), "r"(b[0]), "r"(b[1]));
}
// exact split: v = hi + lo, hi = truncate-to-tf32(v).
__device__ __forceinline__ void split_tf32(float v, unsigned& hi, unsigned& lo) {
    unsigned h = __float_as_uint(v) & 0xFFFFE000u;
    hi = h;
    lo = __float_as_uint(v - __uint_as_float(h));
}

// ---- weight pre-splitter: W (K x J row-major) -> fragment-order packed uint4 ----
__global__ void pack_weights(const float* __restrict__ Wp, const float* __restrict__ Wq,
        const float* __restrict__ Wk, const float* __restrict__ Wv, const float* __restrict__ Wo,
        const float* __restrict__ Wu, const float* __restrict__ Wf1, const float* __restrict__ Wf2,
        const float* __restrict__ Wa, const float* __restrict__ Wout)
{
    const float* src[24]; int Js[24]; long base[24]; int ents[24];
    int n = 0; long off = 0;
    #define ADDSEG(w, K_, J_) { src[n]=(w); Js[n]=(J_); ents[n]=(K_)*(J_)/2; base[n]=off; off+=(K_)*(J_)/2; n++; }
    ADDSEG(Wp, 256, 1024);
    for (int l = 0; l < 3; l++) {
        ADDSEG(Wq+l*16384,128,128); ADDSEG(Wk+l*16384,128,128); ADDSEG(Wv+l*16384,128,128);
        ADDSEG(Wo+l*16384,128,128); ADDSEG(Wu+l*32768,256,128);
        ADDSEG(Wf1+l*65536,128,512); ADDSEG(Wf2+l*65536,512,128);
    }
    ADDSEG(Wa,1024,128); ADDSEG(Wout,128,128);
    #undef ADDSEG
    // n == 24 segments total

    for (long idx = blockIdx.x*(long)blockDim.x + threadIdx.x; idx < PK_TOTAL;
         idx += (long)gridDim.x * blockDim.x) {
        int s = 0;
        while (s < 23 && idx >= base[s] + ents[s]) s++;
        long e = idx - base[s];
        const float* W = src[s]; const int J = Js[s];
        int lane = (int)(e & 31);
        long tmp = e >> 5;
        int jt = (int)(tmp % (J/8));
        int k8 = (int)(tmp / (J/8));
        int tid = lane & 3, group = lane >> 2;
        int ka = k8*8 + tid, j = jt*8 + group;
        float v0 = W[(size_t)ka*J + j];
        float v1 = W[(size_t)(ka+4)*J + j];
        unsigned h0,l0,h1,l1;
        split_tf32(v0,h0,l0); split_tf32(v1,h1,l1);
        g_packed[idx] = make_uint4(h0,l0,h1,l1);
    }
}

// Tensor-core GEMM on pre-split packed weights (pointer-bump addressing).
// out[m][j] = act( sum_k A[m][k]*W[k][j] (+ sum_k2 A2[m][k2]*W[K+k2][j]) + bias[j] )
// A in smem (row-major; optional k-split addressing: elem k at (k/KI)*LDK + k%KI).
// Output col j -> (j/JI)*SJ + j%JI; row m -> (m%MI)*s_in + (m/MI)*s_out.
template<int M,int K,int J,int K2,int MI,int EPI,int KI=1073741824,int LDK=0,int JI=1073741824,int SJ=0>
__device__ __forceinline__ void mma_gemm(
    const float* __restrict__ A,  int lda,
    const float* __restrict__ A2, int lda2,
    const uint4* __restrict__ Wpk,
    const float* __restrict__ bias,
    float* __restrict__ out, int s_in, int s_out)
{
    constexpr int TM16   = (M + 15) / 16;
    constexpr int TJ8    = J / 8;
    constexpr int NWARP  = NT / 32;
    static_assert((TM16 * TJ8) % NWARP == 0, "tile count must divide warps");
    constexpr int NT_S   = TM16 * TJ8 / NWARP;
    constexpr int TJSTEP = NWARP / TM16;
    constexpr bool PRED  = (M % 16) != 0;

    const int w     = threadIdx.x >> 5;
    const int lane  = threadIdx.x & 31;
    const int group = lane >> 2;
    const int tid   = lane & 3;
    const int tm    = w % TM16;
    const int tj0   = w / TM16;
    const int r0    = tm * 16 + group;
    const int r1    = r0 + 8;

    // hoisted base pointers (all hot-loop addressing is pointer + immediate)
    const uint4* wp = Wpk + tj0 * 32 + lane;
    const float* Ar0 = A + r0 * lda;
    const float* Ar1 = A + r1 * lda;

    float acc[NT_S][4];
    #pragma unroll
    for (int s = 0; s < NT_S; s++) { acc[s][0]=0.f; acc[s][1]=0.f; acc[s][2]=0.f; acc[s][3]=0.f; }

    #pragma unroll 2
    for (int k8 = 0; k8 < K; k8 += 8) {
        const int ka = k8 + tid, kb = k8 + tid + 4;
        const int oa = (ka / KI) * LDK + (ka % KI);
        const int ob = (kb / KI) * LDK + (kb % KI);
        float af0, af1, af2, af3;
        if constexpr (!PRED) {
            af0 = Ar0[oa]; af1 = Ar1[oa];
            af2 = Ar0[ob]; af3 = Ar1[ob];
        } else {
            af0 = (r0 < M) ? Ar0[oa] : 0.f;
            af1 = (r1 < M) ? Ar1[oa] : 0.f;
            af2 = (r0 < M) ? Ar0[ob] : 0.f;
            af3 = (r1 < M) ? Ar1[ob] : 0.f;
        }
        unsigned ah[4], al[4];
        split_tf32(af0, ah[0], al[0]); split_tf32(af1, ah[1], al[1]);
        split_tf32(af2, ah[2], al[2]); split_tf32(af3, ah[3], al[3]);
        #pragma unroll
        for (int s = 0; s < NT_S; s++) {
            uint4 b = wp[s * TJSTEP * 32];           // immediate offset
            unsigned bh[2] = {b.x, b.z}, bl[2] = {b.y, b.w};
            mma_tf32(acc[s], ah, bh);
            mma_tf32(acc[s], ah, bl);
            mma_tf32(acc[s], al, bh);
        }
        wp += TJ8 * 32;                              // single pointer bump per k8
    }
    if constexpr (K2 > 0) {
        const float* A2r0 = A2 + r0 * lda2;
        const float* A2r1 = A2 + r1 * lda2;
        #pragma unroll 2
        for (int k8 = 0; k8 < K2; k8 += 8) {
            const int ka = k8 + tid, kb = k8 + tid + 4;
            float af0 = A2r0[ka], af1 = A2r1[ka];
            float af2 = A2r0[kb], af3 = A2r1[kb];
            unsigned ah[4], al[4];
            split_tf32(af0, ah[0], al[0]); split_tf32(af1, ah[1], al[1]);
            split_tf32(af2, ah[2], al[2]); split_tf32(af3, ah[3], al[3]);
            #pragma unroll
            for (int s = 0; s < NT_S; s++) {
                uint4 b = wp[s * TJSTEP * 32];
                unsigned bh[2] = {b.x, b.z}, bl[2] = {b.y, b.w};
                mma_tf32(acc[s], ah, bh);
                mma_tf32(acc[s], ah, bl);
                mma_tf32(acc[s], al, bh);
            }
            wp += TJ8 * 32;
        }
    }

    // epilogue
    #pragma unroll
    for (int s = 0; s < NT_S; s++) {
        const int j0 = (tj0 + s * TJSTEP) * 8;
        const int c0 = j0 + 2 * tid;
        const float b0 = bias[c0], b1 = bias[c0 + 1];
        const int jo = (c0 / JI) * SJ + (c0 % JI);
        float v00 = acc[s][0] + b0, v01 = acc[s][1] + b1;
        float v10 = acc[s][2] + b0, v11 = acc[s][3] + b1;
        if (!PRED || r0 < M) {
            float* p = out + (r0 % MI) * s_in + (r0 / MI) * s_out + jo;
            if constexpr (EPI == EPI_STORE)    { p[0] = v00;              p[1] = v01; }
            if constexpr (EPI == EPI_GELU)     { p[0] = gelu_f(v00);      p[1] = gelu_f(v01); }
            if constexpr (EPI == EPI_ADD)      { p[0] += v00;             p[1] += v01; }
            if constexpr (EPI == EPI_RELU_ADD) { p[0] += fmaxf(v00, 0.f); p[1] += fmaxf(v01, 0.f); }
        }
        if (!PRED || r1 < M) {
            float* p = out + (r1 % MI) * s_in + (r1 / MI) * s_out + jo;
            if constexpr (EPI == EPI_STORE)    { p[0] = v10;              p[1] = v11; }
            if constexpr (EPI == EPI_GELU)     { p[0] = gelu_f(v10);      p[1] = gelu_f(v11); }
            if constexpr (EPI == EPI_ADD)      { p[0] += v10;             p[1] += v11; }
            if constexpr (EPI == EPI_RELU_ADD) { p[0] += fmaxf(v10, 0.f); p[1] += fmaxf(v11, 0.f); }
        }
    }
}

// One LayerNorm over 128 elements: whole warp cooperates (lane owns 4 strided elems)
__device__ __forceinline__ void ln_one(const float* __restrict__ src, float* __restrict__ dst,
                                       const float* __restrict__ g, const float* __restrict__ b)
{
    const int lane = threadIdx.x & 31;
    float v0 = src[lane], v1 = src[lane+32], v2 = src[lane+64], v3 = src[lane+96];
    float s  = v0+v1+v2+v3;
    float sq = v0*v0+v1*v1+v2*v2+v3*v3;
    #pragma unroll
    for (int o = 16; o > 0; o >>= 1) {
        s  += __shfl_xor_sync(0xffffffffu, s,  o);
        sq += __shfl_xor_sync(0xffffffffu, sq, o);
    }
    float mean = s * (1.f/128.f);
    float rstd = rsqrtf(sq * (1.f/128.f) - mean*mean + 1e-5f);
    dst[lane]    = (v0-mean)*rstd*g[lane]    + b[lane];
    dst[lane+32] = (v1-mean)*rstd*g[lane+32] + b[lane+32];
    dst[lane+64] = (v2-mean)*rstd*g[lane+64] + b[lane+64];
    dst[lane+96] = (v3-mean)*rstd*g[lane+96] + b[lane+96];
}

__global__ void __launch_bounds__(NT, 1) fused_reasoner(
    const float* __restrict__ x,
    const float* __restrict__ bp,
    const float* __restrict__ ln1_g, const float* __restrict__ ln1_b,
    const float* __restrict__ bq, const float* __restrict__ bk,
    const float* __restrict__ bv, const float* __restrict__ bo,
    const float* __restrict__ bu,
    const float* __restrict__ ln2_g, const float* __restrict__ ln2_b,
    const float* __restrict__ bf1, const float* __restrict__ bf2,
    const float* __restrict__ ba, const float* __restrict__ bout,
    float* __restrict__ out)
{
    extern __shared__ float S[];
    const int t = threadIdx.x;
    const int wid = t >> 5;            // 0..15
    const int row0 = blockIdx.x * ROWS;

    // ---- stage x tile (8 rows x 256, padded lda=260) into OFF_B ----
    {
        const float4* xg = (const float4*)(x + (size_t)row0 * 256);
        for (int i = t; i < 512; i += NT) {
            int r = i >> 6, c4 = i & 63;               // 64 float4 per row
            *(float4*)(S + OFF_B + r*260 + c4*4) = xg[r*64 + c4];
        }
    }
    __syncthreads();
    // h = x @ Wp + bp : out col j -> H row r*8 + j/128, col j%128
    mma_gemm<8,256,1024,0,8,EPI_STORE, 1073741824,0, 128,LDA>(
        S+OFF_B,260, nullptr,0, g_packed+PK_WP, bp, S+OFF_H, 8*LDA, 0);
    __syncthreads();

    #pragma unroll 1
    for (int l = 0; l < 3; l++) {
        const uint4* pkl = g_packed + PK_L0 + (long)l * PK_LSTR;
        const float* g1 = ln1_g + l*128;   const float* b1 = ln1_b + l*128;
        const float* g2 = ln2_g + l*128;   const float* b2 = ln2_b + l*128;

        // ---- LN1: 64 (row,node) pairs, 16 warps x 4 ----
        #pragma unroll
        for (int it = 0; it < 4; it++) {
            int p = it * 16 + wid;
            ln_one(S + OFF_H + p*LDA, S + OFF_A + p*LDA, g1, b1);
        }
        __syncthreads();

        // ---- Q,K,V projections ----
        mma_gemm<64,128,128,0,64,EPI_STORE>(S+OFF_A,LDA, nullptr,0, pkl+PK_WQ, bq+l*128, S+OFF_D, LDA, 0);
        mma_gemm<64,128,128,0,64,EPI_STORE>(S+OFF_A,LDA, nullptr,0, pkl+PK_WK, bk+l*128, S+OFF_B, LDA, 0);
        mma_gemm<64,128,128,0,64,EPI_STORE>(S+OFF_A,LDA, nullptr,0, pkl+PK_WV, bv+l*128, S+OFF_C, LDA, 0);
        __syncthreads();

        // ---- causal attention: thread = (row, head, query-node); 256 of 512 threads ----
        if (t < 256) {
            const int r = t >> 5, head = (t >> 3) & 3, n = t & 7;
            const float* qp = S + OFF_D + (r*8 + n)*LDA + head*32;
            float p[8];
            float mx = -1e30f;
            #pragma unroll
            for (int m = 0; m < 8; m++) {
                if (m <= n) {
                    const float* kp = S + OFF_B + (r*8 + m)*LDA + head*32;
                    float s = 0.f;
                    #pragma unroll
                    for (int d = 0; d < 32; d++) s += qp[d] * kp[d];
                    s *= 0.17677669529663688f;  // 1/sqrt(32)
                    p[m] = s;
                    mx = fmaxf(mx, s);
                }
            }
            float sum = 0.f;
            #pragma unroll
            for (int m = 0; m < 8; m++) if (m <= n) { p[m] = __expf(p[m] - mx); sum += p[m]; }
            const float inv = 1.f / sum;
            float* ao = S + OFF_D + (r*8 + n)*LDA + head*32;
            #pragma unroll
            for (int d = 0; d < 32; d++) {
                float o = 0.f;
                #pragma unroll
                for (int m = 0; m < 8; m++)
                    if (m <= n) o += p[m] * (S + OFF_C)[(r*8 + m)*LDA + head*32 + d];
                ao[d] = o * inv;
            }
        }
        __syncthreads();

        // ---- attO = att @ Wo + bo  (into OFF_B; k dead) ----
        mma_gemm<64,128,128,0,64,EPI_STORE>(S+OFF_D,LDA, nullptr,0, pkl+PK_WO, bo+l*128, S+OFF_B, LDA, 0);
        __syncthreads();

        // ---- h += relu( [hn | attO] @ Wu + bu ) ----
        mma_gemm<64,128,128,128,64,EPI_RELU_ADD>(S+OFF_A,LDA, S+OFF_B,LDA, pkl+PK_WU, bu+l*128, S+OFF_H, LDA, 0);
        __syncthreads();

        // ---- FFN in 2 chunks of 4 nodes (mid = 32 x 512, lda=516, spans OFF_B..OFF_C) ----
        #pragma unroll 1
        for (int c = 0; c < 2; c++) {
            #pragma unroll
            for (int it = 0; it < 2; it++) {
                int p = it * 16 + wid;            // 0..31 = (r*4 + nn)
                int r = p >> 2, nn = p & 3;
                ln_one(S + OFF_H + (r*8 + c*4 + nn)*LDA, S + OFF_D + p*LDA, g2, b2);
            }
            __syncthreads();
            // mid = gelu(hn2 @ Wf1 + bf1)
            mma_gemm<32,128,512,0,32,EPI_GELU>(S+OFF_D,LDA, nullptr,0, pkl+PK_WF1, bf1+l*512, S+OFF_B, 516, 0);
            __syncthreads();
            // h[:, c*4+nn, :] += mid @ Wf2 + bf2  (row m -> (m%4)*LDA + (m/4)*8*LDA)
            mma_gemm<32,512,128,0,4,EPI_ADD>(S+OFF_B,516, nullptr,0, pkl+PK_WF2, bf2+l*128,
                                             S+OFF_H + c*4*LDA, LDA, 8*LDA);
            __syncthreads();
        }
    }

    // ---- readout: agg = gelu(flat @ Wa + ba)  (flat k -> H row m*8 + k/128, col k%128) ----
    mma_gemm<8,1024,128,0,8,EPI_GELU, 128,LDA>(S+OFF_H, 8*LDA, nullptr,0, g_packed+PK_WA, ba, S+OFF_D, LDA, 0);
    __syncthreads();
    // out = agg @ Wout + bout  (global, unpadded stride 128)
    mma_gemm<8,128,128,0,8,EPI_STORE>(S+OFF_D,LDA, nullptr,0, g_packed+PK_WOUT, bout,
                                      out + (size_t)row0*128, 128, 0);
}

extern "C" void kernel_launch(void* const* d_in, const int* in_sizes, int n_in,
                              void* d_out, int out_size)
{
    (void)n_in; (void)out_size;
    const float* x     = (const float*)d_in[0];
    const float* Wp    = (const float*)d_in[1];
    const float* bp    = (const float*)d_in[2];
    const float* ln1_g = (const float*)d_in[3];
    const float* ln1_b = (const float*)d_in[4];
    const float* Wq    = (const float*)d_in[5];
    const float* bq    = (const float*)d_in[6];
    const float* Wk    = (const float*)d_in[7];
    const float* bk    = (const float*)d_in[8];
    const float* Wv    = (const float*)d_in[9];
    const float* bv    = (const float*)d_in[10];
    const float* Wo    = (const float*)d_in[11];
    const float* bo    = (const float*)d_in[12];
    const float* Wu    = (const float*)d_in[13];
    const float* bu    = (const float*)d_in[14];
    const float* ln2_g = (const float*)d_in[15];
    const float* ln2_b = (const float*)d_in[16];
    const float* Wf1   = (const float*)d_in[17];
    const float* bf1   = (const float*)d_in[18];
    const float* Wf2   = (const float*)d_in[19];
    const float* bf2   = (const float*)d_in[20];
    const float* Wa    = (const float*)d_in[21];
    const float* ba    = (const float*)d_in[22];
    const float* Wout  = (const float*)d_in[23];
    const float* bout  = (const float*)d_in[24];

    const int Bsz = in_sizes[0] / 256;       // DIN = 256
    const int grid = Bsz / ROWS;             // B divisible by 8
    const size_t smem = SMEM_FLOATS * sizeof(float);

    pack_weights<<<2144, 256>>>(Wp, Wq, Wk, Wv, Wo, Wu, Wf1, Wf2, Wa, Wout);

    cudaFuncSetAttribute(fused_reasoner, cudaFuncAttributeMaxDynamicSharedMemorySize, (int)smem);
    fused_reasoner<<<grid, NT, smem>>>(
        x, bp, ln1_g, ln1_b, bq, bk, bv, bo, bu, ln2_g, ln2_b,
        bf1, bf2, ba, bout, (float*)d_out);
}

// round 9
// speedup vs baseline: 5.9568x; 1.5771x over previous
#include <cuda_runtime.h>
#include <math.h>

#define NT 512
#define ROWS 8
#define LDA 132            // padded row stride for 128-wide activations (132%32==4 -> conflict-free)

// shared memory layout (in floats); each main buffer holds 64 rows x LDA
#define OFF_H 0
#define OFF_A 8448
#define OFF_B 16896
#define OFF_C 25344
#define OFF_D 33792
#define SMEM_FLOATS 42240   // 168,960 bytes

// ---- packed (pre-split bf16) weight scratch: uint4{bh0,bh1,bl0,bl1} per [k16][jt][lane] ----
#define PK_WP     0          // 256*1024/4 = 65536
#define PK_L0     65536
#define PK_LSTR   57344      // per layer: 4*4096 + 8192 + 2*16384
#define PK_WQ     0
#define PK_WK     4096
#define PK_WV     8192
#define PK_WO     12288
#define PK_WU     16384
#define PK_WF1    24576
#define PK_WF2    40960
#define PK_WA     237568     // 65536 + 3*57344
#define PK_WOUT   270336
#define PK_TOTAL  274432

__device__ uint4 g_packed[PK_TOTAL];

enum { EPI_STORE=0, EPI_GELU=2, EPI_ADD=3, EPI_RELU_ADD=4 };

__device__ __forceinline__ float gelu_f(float v) {
    return 0.5f * v * (1.0f + erff(v * 0.70710678118654752440f));
}

// ---- bf16 mma helpers ----
__device__ __forceinline__ void mma_bf16(float* d, const unsigned* a, const unsigned* b) {
    asm("mma.sync.aligned.m16n8k16.row.col.f32.bf16.bf16.f32 "
        "{%0,%1,%2,%3}, {%4,%5,%6,%7}, {%8,%9}, {%0,%1,%2,%3};"
        : "+f"(d[0]), "+f"(d[1]), "+f"(d[2]), "+f"(d[3])
        : "r"(a[0]), "r"(a[1]), "r"(a[2]), "r"(a[3]), "r"(b[0]), "r"(b[1]));
}
// pack two floats -> bf16x2 (upper = hi_elem, lower = lo_elem)
__device__ __forceinline__ unsigned cvt_bf16x2(float hi_elem, float lo_elem) {
    unsigned r;
    asm("cvt.rn.bf16x2.f32 %0, %1, %2;" : "=r"(r) : "f"(hi_elem), "f"(lo_elem));
    return r;
}
__device__ __forceinline__ float bf_lo(unsigned r) { return __uint_as_float(r << 16); }
__device__ __forceinline__ float bf_hi(unsigned r) { return __uint_as_float(r & 0xFFFF0000u); }
// split pair (x = elem k, y = elem k+1) into hi/lo bf16x2 fragment regs
__device__ __forceinline__ void split_bf16(float x, float y, unsigned& hi, unsigned& lo) {
    hi = cvt_bf16x2(y, x);
    lo = cvt_bf16x2(y - bf_hi(hi), x - bf_lo(hi));
}

// ---- weight pre-splitter: W (K x J row-major) -> fragment-order packed bf16 uint4 ----
__global__ void pack_weights(const float* __restrict__ Wp, const float* __restrict__ Wq,
        const float* __restrict__ Wk, const float* __restrict__ Wv, const float* __restrict__ Wo,
        const float* __restrict__ Wu, const float* __restrict__ Wf1, const float* __restrict__ Wf2,
        const float* __restrict__ Wa, const float* __restrict__ Wout)
{
    const float* src[24]; int Js[24]; long base[24]; int ents[24];
    int n = 0; long off = 0;
    #define ADDSEG(w, K_, J_) { src[n]=(w); Js[n]=(J_); ents[n]=(K_)*(J_)/4; base[n]=off; off+=(K_)*(J_)/4; n++; }
    ADDSEG(Wp, 256, 1024);
    for (int l = 0; l < 3; l++) {
        ADDSEG(Wq+l*16384,128,128); ADDSEG(Wk+l*16384,128,128); ADDSEG(Wv+l*16384,128,128);
        ADDSEG(Wo+l*16384,128,128); ADDSEG(Wu+l*32768,256,128);
        ADDSEG(Wf1+l*65536,128,512); ADDSEG(Wf2+l*65536,512,128);
    }
    ADDSEG(Wa,1024,128); ADDSEG(Wout,128,128);
    #undef ADDSEG
    // 24 segments total

    for (long idx = blockIdx.x*(long)blockDim.x + threadIdx.x; idx < PK_TOTAL;
         idx += (long)gridDim.x * blockDim.x) {
        int s = 0;
        while (s < 23 && idx >= base[s] + ents[s]) s++;
        long e = idx - base[s];
        const float* W = src[s]; const int J = Js[s];
        int lane = (int)(e & 31);
        long tmp = e >> 5;
        int jt  = (int)(tmp % (J/8));
        int k16 = (int)(tmp / (J/8));
        int tid = lane & 3, group = lane >> 2;
        int j  = jt*8 + group;
        int k0 = k16*16 + 2*tid;
        float w0 = W[(size_t)(k0  )*J + j];
        float w1 = W[(size_t)(k0+1)*J + j];
        float w2 = W[(size_t)(k0+8)*J + j];
        float w3 = W[(size_t)(k0+9)*J + j];
        unsigned bh0, bl0, bh1, bl1;
        split_bf16(w0, w1, bh0, bl0);
        split_bf16(w2, w3, bh1, bl1);
        g_packed[idx] = make_uint4(bh0, bh1, bl0, bl1);
    }
}

// Tensor-core GEMM on pre-split packed bf16 weights (pointer-bump addressing).
// out[m][j] = act( sum_k A[m][k]*W[k][j] (+ sum_k2 A2[m][k2]*W[K+k2][j]) + bias[j] )
// A fp32 in smem (row-major; optional k-split addressing: elem k at (k/KI)*LDK + k%KI).
// Output col j -> (j/JI)*SJ + j%JI; row m -> (m%MI)*s_in + (m/MI)*s_out.
// m16n8k16 bf16 with 3-way hi/lo split (ah*bh + ah*bl + al*bh), fp32 accumulate.
template<int M,int K,int J,int K2,int MI,int EPI,int KI=1073741824,int LDK=0,int JI=1073741824,int SJ=0>
__device__ __forceinline__ void mma_gemm(
    const float* __restrict__ A,  int lda,
    const float* __restrict__ A2, int lda2,
    const uint4* __restrict__ Wpk,
    const float* __restrict__ bias,
    float* __restrict__ out, int s_in, int s_out)
{
    constexpr int TM16   = (M + 15) / 16;
    constexpr int TJ8    = J / 8;
    constexpr int NWARP  = NT / 32;
    static_assert((TM16 * TJ8) % NWARP == 0, "tile count must divide warps");
    constexpr int NT_S   = TM16 * TJ8 / NWARP;
    constexpr int TJSTEP = NWARP / TM16;
    constexpr bool PRED  = (M % 16) != 0;

    const int w     = threadIdx.x >> 5;
    const int lane  = threadIdx.x & 31;
    const int group = lane >> 2;
    const int tid   = lane & 3;
    const int tm    = w % TM16;
    const int tj0   = w / TM16;
    const int r0    = tm * 16 + group;
    const int r1    = r0 + 8;

    // hoisted base pointers
    const uint4* wp = Wpk + tj0 * 32 + lane;
    const float* Ar0 = A + r0 * lda;
    const float* Ar1 = A + r1 * lda;

    float acc[NT_S][4];
    #pragma unroll
    for (int s = 0; s < NT_S; s++) { acc[s][0]=0.f; acc[s][1]=0.f; acc[s][2]=0.f; acc[s][3]=0.f; }

    #pragma unroll 2
    for (int k16 = 0; k16 < K; k16 += 16) {
        const int ka = k16 + 2*tid;          // pair (ka, ka+1)
        const int kb = ka + 8;               // pair (kb, kb+1); never crosses KI boundary
        const int oa = (ka / KI) * LDK + (ka % KI);
        const int ob = (kb / KI) * LDK + (kb % KI);
        float2 av0, av1, av2, av3;
        if constexpr (!PRED) {
            av0 = *(const float2*)(Ar0 + oa); av1 = *(const float2*)(Ar1 + oa);
            av2 = *(const float2*)(Ar0 + ob); av3 = *(const float2*)(Ar1 + ob);
        } else {
            av0 = (r0 < M) ? *(const float2*)(Ar0 + oa) : make_float2(0.f, 0.f);
            av1 = (r1 < M) ? *(const float2*)(Ar1 + oa) : make_float2(0.f, 0.f);
            av2 = (r0 < M) ? *(const float2*)(Ar0 + ob) : make_float2(0.f, 0.f);
            av3 = (r1 < M) ? *(const float2*)(Ar1 + ob) : make_float2(0.f, 0.f);
        }
        unsigned ah[4], al[4];
        split_bf16(av0.x, av0.y, ah[0], al[0]);
        split_bf16(av1.x, av1.y, ah[1], al[1]);
        split_bf16(av2.x, av2.y, ah[2], al[2]);
        split_bf16(av3.x, av3.y, ah[3], al[3]);
        #pragma unroll
        for (int s = 0; s < NT_S; s++) {
            uint4 b = wp[s * TJSTEP * 32];   // immediate offset
            unsigned bh[2] = {b.x, b.y}, bl[2] = {b.z, b.w};
            mma_bf16(acc[s], ah, bh);
            mma_bf16(acc[s], ah, bl);
            mma_bf16(acc[s], al, bh);
        }
        wp += TJ8 * 32;                      // one pointer bump per k16
    }
    if constexpr (K2 > 0) {
        const float* A2r0 = A2 + r0 * lda2;
        const float* A2r1 = A2 + r1 * lda2;
        #pragma unroll 2
        for (int k16 = 0; k16 < K2; k16 += 16) {
            const int ka = k16 + 2*tid, kb = ka + 8;
            float2 av0 = *(const float2*)(A2r0 + ka);
            float2 av1 = *(const float2*)(A2r1 + ka);
            float2 av2 = *(const float2*)(A2r0 + kb);
            float2 av3 = *(const float2*)(A2r1 + kb);
            unsigned ah[4], al[4];
            split_bf16(av0.x, av0.y, ah[0], al[0]);
            split_bf16(av1.x, av1.y, ah[1], al[1]);
            split_bf16(av2.x, av2.y, ah[2], al[2]);
            split_bf16(av3.x, av3.y, ah[3], al[3]);
            #pragma unroll
            for (int s = 0; s < NT_S; s++) {
                uint4 b = wp[s * TJSTEP * 32];
                unsigned bh[2] = {b.x, b.y}, bl[2] = {b.z, b.w};
                mma_bf16(acc[s], ah, bh);
                mma_bf16(acc[s], ah, bl);
                mma_bf16(acc[s], al, bh);
            }
            wp += TJ8 * 32;
        }
    }

    // epilogue (C layout of m16n8k16 == m16n8k8: c0,c1 row r0 cols 2*tid,2*tid+1; c2,c3 row r1)
    #pragma unroll
    for (int s = 0; s < NT_S; s++) {
        const int j0 = (tj0 + s * TJSTEP) * 8;
        const int c0 = j0 + 2 * tid;
        const float b0 = bias[c0], b1 = bias[c0 + 1];
        const int jo = (c0 / JI) * SJ + (c0 % JI);
        float v00 = acc[s][0] + b0, v01 = acc[s][1] + b1;
        float v10 = acc[s][2] + b0, v11 = acc[s][3] + b1;
        if (!PRED || r0 < M) {
            float* p = out + (r0 % MI) * s_in + (r0 / MI) * s_out + jo;
            if constexpr (EPI == EPI_STORE)    { p[0] = v00;              p[1] = v01; }
            if constexpr (EPI == EPI_GELU)     { p[0] = gelu_f(v00);      p[1] = gelu_f(v01); }
            if constexpr (EPI == EPI_ADD)      { p[0] += v00;             p[1] += v01; }
            if constexpr (EPI == EPI_RELU_ADD) { p[0] += fmaxf(v00, 0.f); p[1] += fmaxf(v01, 0.f); }
        }
        if (!PRED || r1 < M) {
            float* p = out + (r1 % MI) * s_in + (r1 / MI) * s_out + jo;
            if constexpr (EPI == EPI_STORE)    { p[0] = v10;              p[1] = v11; }
            if constexpr (EPI == EPI_GELU)     { p[0] = gelu_f(v10);      p[1] = gelu_f(v11); }
            if constexpr (EPI == EPI_ADD)      { p[0] += v10;             p[1] += v11; }
            if constexpr (EPI == EPI_RELU_ADD) { p[0] += fmaxf(v10, 0.f); p[1] += fmaxf(v11, 0.f); }
        }
    }
}

// One LayerNorm over 128 elements: whole warp cooperates (lane owns 4 strided elems)
__device__ __forceinline__ void ln_one(const float* __restrict__ src, float* __restrict__ dst,
                                       const float* __restrict__ g, const float* __restrict__ b)
{
    const int lane = threadIdx.x & 31;
    float v0 = src[lane], v1 = src[lane+32], v2 = src[lane+64], v3 = src[lane+96];
    float s  = v0+v1+v2+v3;
    float sq = v0*v0+v1*v1+v2*v2+v3*v3;
    #pragma unroll
    for (int o = 16; o > 0; o >>= 1) {
        s  += __shfl_xor_sync(0xffffffffu, s,  o);
        sq += __shfl_xor_sync(0xffffffffu, sq, o);
    }
    float mean = s * (1.f/128.f);
    float rstd = rsqrtf(sq * (1.f/128.f) - mean*mean + 1e-5f);
    dst[lane]    = (v0-mean)*rstd*g[lane]    + b[lane];
    dst[lane+32] = (v1-mean)*rstd*g[lane+32] + b[lane+32];
    dst[lane+64] = (v2-mean)*rstd*g[lane+64] + b[lane+64];
    dst[lane+96] = (v3-mean)*rstd*g[lane+96] + b[lane+96];
}

__global__ void __launch_bounds__(NT, 1) fused_reasoner(
    const float* __restrict__ x,
    const float* __restrict__ bp,
    const float* __restrict__ ln1_g, const float* __restrict__ ln1_b,
    const float* __restrict__ bq, const float* __restrict__ bk,
    const float* __restrict__ bv, const float* __restrict__ bo,
    const float* __restrict__ bu,
    const float* __restrict__ ln2_g, const float* __restrict__ ln2_b,
    const float* __restrict__ bf1, const float* __restrict__ bf2,
    const float* __restrict__ ba, const float* __restrict__ bout,
    float* __restrict__ out)
{
    extern __shared__ float S[];
    const int t = threadIdx.x;
    const int wid = t >> 5;            // 0..15
    const int row0 = blockIdx.x * ROWS;

    // ---- stage x tile (8 rows x 256, padded lda=260) into OFF_B ----
    {
        const float4* xg = (const float4*)(x + (size_t)row0 * 256);
        for (int i = t; i < 512; i += NT) {
            int r = i >> 6, c4 = i & 63;               // 64 float4 per row
            *(float4*)(S + OFF_B + r*260 + c4*4) = xg[r*64 + c4];
        }
    }
    __syncthreads();
    // h = x @ Wp + bp : out col j -> H row r*8 + j/128, col j%128
    mma_gemm<8,256,1024,0,8,EPI_STORE, 1073741824,0, 128,LDA>(
        S+OFF_B,260, nullptr,0, g_packed+PK_WP, bp, S+OFF_H, 8*LDA, 0);
    __syncthreads();

    #pragma unroll 1
    for (int l = 0; l < 3; l++) {
        const uint4* pkl = g_packed + PK_L0 + (long)l * PK_LSTR;
        const float* g1 = ln1_g + l*128;   const float* b1 = ln1_b + l*128;
        const float* g2 = ln2_g + l*128;   const float* b2 = ln2_b + l*128;

        // ---- LN1: 64 (row,node) pairs, 16 warps x 4 ----
        #pragma unroll
        for (int it = 0; it < 4; it++) {
            int p = it * 16 + wid;
            ln_one(S + OFF_H + p*LDA, S + OFF_A + p*LDA, g1, b1);
        }
        __syncthreads();

        // ---- Q,K,V projections ----
        mma_gemm<64,128,128,0,64,EPI_STORE>(S+OFF_A,LDA, nullptr,0, pkl+PK_WQ, bq+l*128, S+OFF_D, LDA, 0);
        mma_gemm<64,128,128,0,64,EPI_STORE>(S+OFF_A,LDA, nullptr,0, pkl+PK_WK, bk+l*128, S+OFF_B, LDA, 0);
        mma_gemm<64,128,128,0,64,EPI_STORE>(S+OFF_A,LDA, nullptr,0, pkl+PK_WV, bv+l*128, S+OFF_C, LDA, 0);
        __syncthreads();

        // ---- causal attention: thread = (row, head, query-node); 256 of 512 threads ----
        if (t < 256) {
            const int r = t >> 5, head = (t >> 3) & 3, n = t & 7;
            const float* qp = S + OFF_D + (r*8 + n)*LDA + head*32;
            float p[8];
            float mx = -1e30f;
            #pragma unroll
            for (int m = 0; m < 8; m++) {
                if (m <= n) {
                    const float* kp = S + OFF_B + (r*8 + m)*LDA + head*32;
                    float s = 0.f;
                    #pragma unroll
                    for (int d = 0; d < 32; d++) s += qp[d] * kp[d];
                    s *= 0.17677669529663688f;  // 1/sqrt(32)
                    p[m] = s;
                    mx = fmaxf(mx, s);
                }
            }
            float sum = 0.f;
            #pragma unroll
            for (int m = 0; m < 8; m++) if (m <= n) { p[m] = __expf(p[m] - mx); sum += p[m]; }
            const float inv = 1.f / sum;
            float* ao = S + OFF_D + (r*8 + n)*LDA + head*32;
            #pragma unroll
            for (int d = 0; d < 32; d++) {
                float o = 0.f;
                #pragma unroll
                for (int m = 0; m < 8; m++)
                    if (m <= n) o += p[m] * (S + OFF_C)[(r*8 + m)*LDA + head*32 + d];
                ao[d] = o * inv;
            }
        }
        __syncthreads();

        // ---- attO = att @ Wo + bo  (into OFF_B; k dead) ----
        mma_gemm<64,128,128,0,64,EPI_STORE>(S+OFF_D,LDA, nullptr,0, pkl+PK_WO, bo+l*128, S+OFF_B, LDA, 0);
        __syncthreads();

        // ---- h += relu( [hn | attO] @ Wu + bu ) ----
        mma_gemm<64,128,128,128,64,EPI_RELU_ADD>(S+OFF_A,LDA, S+OFF_B,LDA, pkl+PK_WU, bu+l*128, S+OFF_H, LDA, 0);
        __syncthreads();

        // ---- FFN in 2 chunks of 4 nodes (mid = 32 x 512, lda=516, spans OFF_B..OFF_C) ----
        #pragma unroll 1
        for (int c = 0; c < 2; c++) {
            #pragma unroll
            for (int it = 0; it < 2; it++) {
                int p = it * 16 + wid;            // 0..31 = (r*4 + nn)
                int r = p >> 2, nn = p & 3;
                ln_one(S + OFF_H + (r*8 + c*4 + nn)*LDA, S + OFF_D + p*LDA, g2, b2);
            }
            __syncthreads();
            // mid = gelu(hn2 @ Wf1 + bf1)
            mma_gemm<32,128,512,0,32,EPI_GELU>(S+OFF_D,LDA, nullptr,0, pkl+PK_WF1, bf1+l*512, S+OFF_B, 516, 0);
            __syncthreads();
            // h[:, c*4+nn, :] += mid @ Wf2 + bf2  (row m -> (m%4)*LDA + (m/4)*8*LDA)
            mma_gemm<32,512,128,0,4,EPI_ADD>(S+OFF_B,516, nullptr,0, pkl+PK_WF2, bf2+l*128,
                                             S+OFF_H + c*4*LDA, LDA, 8*LDA);
            __syncthreads();
        }
    }

    // ---- readout: agg = gelu(flat @ Wa + ba)  (flat k -> H row m*8 + k/128, col k%128) ----
    mma_gemm<8,1024,128,0,8,EPI_GELU, 128,LDA>(S+OFF_H, 8*LDA, nullptr,0, g_packed+PK_WA, ba, S+OFF_D, LDA, 0);
    __syncthreads();
    // out = agg @ Wout + bout  (global, unpadded stride 128)
    mma_gemm<8,128,128,0,8,EPI_STORE>(S+OFF_D,LDA, nullptr,0, g_packed+PK_WOUT, bout,
                                      out + (size_t)row0*128, 128, 0);
}

extern "C" void kernel_launch(void* const* d_in, const int* in_sizes, int n_in,
                              void* d_out, int out_size)
{
    (void)n_in; (void)out_size;
    const float* x     = (const float*)d_in[0];
    const float* Wp    = (const float*)d_in[1];
    const float* bp    = (const float*)d_in[2];
    const float* ln1_g = (const float*)d_in[3];
    const float* ln1_b = (const float*)d_in[4];
    const float* Wq    = (const float*)d_in[5];
    const float* bq    = (const float*)d_in[6];
    const float* Wk    = (const float*)d_in[7];
    const float* bk    = (const float*)d_in[8];
    const float* Wv    = (const float*)d_in[9];
    const float* bv    = (const float*)d_in[10];
    const float* Wo    = (const float*)d_in[11];
    const float* bo    = (const float*)d_in[12];
    const float* Wu    = (const float*)d_in[13];
    const float* bu    = (const float*)d_in[14];
    const float* ln2_g = (const float*)d_in[15];
    const float* ln2_b = (const float*)d_in[16];
    const float* Wf1   = (const float*)d_in[17];
    const float* bf1   = (const float*)d_in[18];
    const float* Wf2   = (const float*)d_in[19];
    const float* bf2   = (const float*)d_in[20];
    const float* Wa    = (const float*)d_in[21];
    const float* ba    = (const float*)d_in[22];
    const float* Wout  = (const float*)d_in[23];
    const float* bout  = (const float*)d_in[24];

    const int Bsz = in_sizes[0] / 256;       // DIN = 256
    const int grid = Bsz / ROWS;             // B divisible by 8
    const size_t smem = SMEM_FLOATS * sizeof(float);

    pack_weights<<<1072, 256>>>(Wp, Wq, Wk, Wv, Wo, Wu, Wf1, Wf2, Wa, Wout);

    cudaFuncSetAttribute(fused_reasoner, cudaFuncAttributeMaxDynamicSharedMemorySize, (int)smem);
    fused_reasoner<<<grid, NT, smem>>>(
        x, bp, ln1_g, ln1_b, bq, bk, bv, bo, bu, ln2_g, ln2_b,
        bf1, bf2, ba, bout, (float*)d_out);
}

// round 10
// speedup vs baseline: 6.3125x; 1.0597x over previous
#include <cuda_runtime.h>
#include <math.h>

#define NT 512
#define ROWS 8
#define LDH 132            // fp32 H row stride (132%32==4)

// ---- smem regions (u32 units) ----
#define OFF_H    0         // H fp32: 64 x 132            = 8448
#define OFF_SP1  8448      // hn split 64x144 / splitH 8x1168 = 9344
#define OFF_FK   17792     // K fp32 64x132; FFN: mid split (32x528 spans FK+FV)
#define OFF_FV   26240     // V fp32 64x132
#define OFF_QA   34688     // Q fp32 64x132 / att split 64x144 / hn2 split 32x144
#define OFF_SP2  43904     // x split 8x272 / attO split 64x144 / agg split 8x144
#define SMEM_U32 53120     // 212,480 bytes

// ---- packed (pre-split bf16) weight scratch: uint4{bh0,bh1,bl0,bl1} per [k16][jt][lane] ----
#define PK_WP     0
#define PK_L0     65536
#define PK_LSTR   57344
#define PK_WQ     0
#define PK_WK     4096
#define PK_WV     8192
#define PK_WO     12288
#define PK_WU     16384
#define PK_WF1    24576
#define PK_WF2    40960
#define PK_WA     237568
#define PK_WOUT   270336
#define PK_TOTAL  274432

__device__ uint4 g_packed[PK_TOTAL];

enum { EPI_STORE=0, EPI_GELU=2, EPI_ADD=3, EPI_RELU_ADD=4 };

__device__ __forceinline__ float gelu_f(float v) {
    return 0.5f * v * (1.0f + erff(v * 0.70710678118654752440f));
}

// ---- bf16 mma helpers ----
__device__ __forceinline__ void mma_bf16(float* d, const unsigned* a, const unsigned* b) {
    asm("mma.sync.aligned.m16n8k16.row.col.f32.bf16.bf16.f32 "
        "{%0,%1,%2,%3}, {%4,%5,%6,%7}, {%8,%9}, {%0,%1,%2,%3};"
        : "+f"(d[0]), "+f"(d[1]), "+f"(d[2]), "+f"(d[3])
        : "r"(a[0]), "r"(a[1]), "r"(a[2]), "r"(a[3]), "r"(b[0]), "r"(b[1]));
}
__device__ __forceinline__ unsigned cvt_bf16x2(float hi_elem, float lo_elem) {
    unsigned r;
    asm("cvt.rn.bf16x2.f32 %0, %1, %2;" : "=r"(r) : "f"(hi_elem), "f"(lo_elem));
    return r;
}
__device__ __forceinline__ float bf_lo(unsigned r) { return __uint_as_float(r << 16); }
__device__ __forceinline__ float bf_hi(unsigned r) { return __uint_as_float(r & 0xFFFF0000u); }
// split pair (x = elem k, y = elem k+1) into hi/lo bf16x2 regs
__device__ __forceinline__ void split_bf16(float x, float y, unsigned& hi, unsigned& lo) {
    hi = cvt_bf16x2(y, x);
    lo = cvt_bf16x2(y - bf_hi(hi), x - bf_lo(hi));
}
// slot (u32 offset within 16-u32 window) of pair p (0..7)
__device__ __forceinline__ int pslot(int p) { return (p < 4) ? p * 4 : (p - 4) * 4 + 2; }
// write split pair {x,y} at (window w, pair p) of a split row
__device__ __forceinline__ void store_split_pair(unsigned* row, int w, int p, float x, float y) {
    unsigned hi, lo; split_bf16(x, y, hi, lo);
    *(uint2*)(row + w * 16 + pslot(p)) = make_uint2(hi, lo);
}

// ---- weight pre-splitter (same format as R9) ----
__global__ void pack_weights(const float* __restrict__ Wp, const float* __restrict__ Wq,
        const float* __restrict__ Wk, const float* __restrict__ Wv, const float* __restrict__ Wo,
        const float* __restrict__ Wu, const float* __restrict__ Wf1, const float* __restrict__ Wf2,
        const float* __restrict__ Wa, const float* __restrict__ Wout)
{
    const float* src[24]; int Js[24]; long base[24]; int ents[24];
    int n = 0; long off = 0;
    #define ADDSEG(w, K_, J_) { src[n]=(w); Js[n]=(J_); ents[n]=(K_)*(J_)/4; base[n]=off; off+=(K_)*(J_)/4; n++; }
    ADDSEG(Wp, 256, 1024);
    for (int l = 0; l < 3; l++) {
        ADDSEG(Wq+l*16384,128,128); ADDSEG(Wk+l*16384,128,128); ADDSEG(Wv+l*16384,128,128);
        ADDSEG(Wo+l*16384,128,128); ADDSEG(Wu+l*32768,256,128);
        ADDSEG(Wf1+l*65536,128,512); ADDSEG(Wf2+l*65536,512,128);
    }
    ADDSEG(Wa,1024,128); ADDSEG(Wout,128,128);
    #undef ADDSEG

    for (long idx = blockIdx.x*(long)blockDim.x + threadIdx.x; idx < PK_TOTAL;
         idx += (long)gridDim.x * blockDim.x) {
        int s = 0;
        while (s < 23 && idx >= base[s] + ents[s]) s++;
        long e = idx - base[s];
        const float* W = src[s]; const int J = Js[s];
        int lane = (int)(e & 31);
        long tmp = e >> 5;
        int jt  = (int)(tmp % (J/8));
        int k16 = (int)(tmp / (J/8));
        int tid = lane & 3, group = lane >> 2;
        int j  = jt*8 + group;
        int k0 = k16*16 + 2*tid;
        float w0 = W[(size_t)(k0  )*J + j];
        float w1 = W[(size_t)(k0+1)*J + j];
        float w2 = W[(size_t)(k0+8)*J + j];
        float w3 = W[(size_t)(k0+9)*J + j];
        unsigned bh0, bl0, bh1, bl1;
        split_bf16(w0, w1, bh0, bl0);
        split_bf16(w2, w3, bh1, bl1);
        g_packed[idx] = make_uint4(bh0, bh1, bl0, bl1);
    }
}

// Tensor-core GEMM: A pre-split in smem (u32 window-permuted), B pre-split packed in global.
// out[m][j] = act( sum_k A[m][k]*W[k][j] (+ sum_k2 A2[m][k2]*W[K+k2][j]) + bias[j] )
// A window offset for k16 index ii: (ii/KI16)*LDKW + (ii%KI16)*16.
// OSPLIT: out is split u32 buffer (row stride s_in u32); else fp32 with col map (j/JI)*SJ + j%JI
// and row map (m%MI)*s_in + (m/MI)*s_out.
template<int M,int K,int J,int K2,int MI,int EPI,bool OSPLIT,int KI16=1<<28,int LDKW=0,int JI=1<<28,int SJ=0>
__device__ __forceinline__ void mma_gemm(
    const unsigned* __restrict__ A,  int lda,
    const unsigned* __restrict__ A2, int lda2,
    const uint4* __restrict__ Wpk,
    const float* __restrict__ bias,
    void* __restrict__ outp, int s_in, int s_out)
{
    constexpr int TM16   = (M + 15) / 16;
    constexpr int TJ8    = J / 8;
    constexpr int NWARP  = NT / 32;
    static_assert((TM16 * TJ8) % NWARP == 0, "tile count must divide warps");
    constexpr int NT_S   = TM16 * TJ8 / NWARP;
    constexpr int TJSTEP = NWARP / TM16;
    constexpr bool PRED  = (M % 16) != 0;

    const int w     = threadIdx.x >> 5;
    const int lane  = threadIdx.x & 31;
    const int group = lane >> 2;
    const int tid   = lane & 3;
    const int tm    = w % TM16;
    const int tj0   = w / TM16;
    const int r0    = tm * 16 + group;
    const int r1    = r0 + 8;

    const uint4* wp = Wpk + tj0 * 32 + lane;
    const unsigned* Ar0 = A + r0 * lda + tid * 4;
    const unsigned* Ar1 = A + r1 * lda + tid * 4;

    float acc[NT_S][4];
    #pragma unroll
    for (int s = 0; s < NT_S; s++) { acc[s][0]=0.f; acc[s][1]=0.f; acc[s][2]=0.f; acc[s][3]=0.f; }

    #pragma unroll 2
    for (int ii = 0; ii < K/16; ii++) {
        const int woff = (ii / KI16) * LDKW + (ii % KI16) * 16;
        uint4 a0, a1;
        if (!PRED || r0 < M) a0 = *(const uint4*)(Ar0 + woff); else a0 = make_uint4(0,0,0,0);
        if (!PRED || r1 < M) a1 = *(const uint4*)(Ar1 + woff); else a1 = make_uint4(0,0,0,0);
        unsigned ah[4] = {a0.x, a1.x, a0.z, a1.z};
        unsigned al[4] = {a0.y, a1.y, a0.w, a1.w};
        #pragma unroll
        for (int s = 0; s < NT_S; s++) {
            uint4 b = wp[s * TJSTEP * 32];
            unsigned bh[2] = {b.x, b.y}, bl[2] = {b.z, b.w};
            mma_bf16(acc[s], ah, bh);
            mma_bf16(acc[s], ah, bl);
            mma_bf16(acc[s], al, bh);
        }
        wp += TJ8 * 32;
    }
    if constexpr (K2 > 0) {
        const unsigned* B0 = A2 + r0 * lda2 + tid * 4;
        const unsigned* B1 = A2 + r1 * lda2 + tid * 4;
        #pragma unroll 2
        for (int ii = 0; ii < K2/16; ii++) {
            uint4 a0 = *(const uint4*)(B0 + ii * 16);
            uint4 a1 = *(const uint4*)(B1 + ii * 16);
            unsigned ah[4] = {a0.x, a1.x, a0.z, a1.z};
            unsigned al[4] = {a0.y, a1.y, a0.w, a1.w};
            #pragma unroll
            for (int s = 0; s < NT_S; s++) {
                uint4 b = wp[s * TJSTEP * 32];
                unsigned bh[2] = {b.x, b.y}, bl[2] = {b.z, b.w};
                mma_bf16(acc[s], ah, bh);
                mma_bf16(acc[s], ah, bl);
                mma_bf16(acc[s], al, bh);
            }
            wp += TJ8 * 32;
        }
    }

    // epilogue: c0..c1 = row r0 cols (c0,c0+1); c2..c3 = row r1
    #pragma unroll
    for (int s = 0; s < NT_S; s++) {
        const int j0 = (tj0 + s * TJSTEP) * 8;
        const int c0 = j0 + 2 * tid;
        const float b0 = bias[c0], b1 = bias[c0 + 1];
        float v00 = acc[s][0] + b0, v01 = acc[s][1] + b1;
        float v10 = acc[s][2] + b0, v11 = acc[s][3] + b1;
        if constexpr (EPI == EPI_GELU) { v00=gelu_f(v00); v01=gelu_f(v01); v10=gelu_f(v10); v11=gelu_f(v11); }
        if constexpr (OSPLIT) {
            unsigned* ob = (unsigned*)outp;
            const int off = (c0 >> 4) * 16 + tid * 4 + ((j0 >> 3) & 1) * 2;
            if (!PRED || r0 < M) {
                unsigned hi, lo; split_bf16(v00, v01, hi, lo);
                *(uint2*)(ob + r0 * s_in + off) = make_uint2(hi, lo);
            }
            if (!PRED || r1 < M) {
                unsigned hi, lo; split_bf16(v10, v11, hi, lo);
                *(uint2*)(ob + r1 * s_in + off) = make_uint2(hi, lo);
            }
        } else {
            float* of = (float*)outp;
            const int jo = (c0 / JI) * SJ + (c0 % JI);
            if (!PRED || r0 < M) {
                float* p = of + (r0 % MI) * s_in + (r0 / MI) * s_out + jo;
                if constexpr (EPI == EPI_ADD)      { p[0] += v00; p[1] += v01; }
                else if constexpr (EPI == EPI_RELU_ADD) { p[0] += fmaxf(v00,0.f); p[1] += fmaxf(v01,0.f); }
                else { p[0] = v00; p[1] = v01; }
            }
            if (!PRED || r1 < M) {
                float* p = of + (r1 % MI) * s_in + (r1 / MI) * s_out + jo;
                if constexpr (EPI == EPI_ADD)      { p[0] += v10; p[1] += v11; }
                else if constexpr (EPI == EPI_RELU_ADD) { p[0] += fmaxf(v10,0.f); p[1] += fmaxf(v11,0.f); }
                else { p[0] = v10; p[1] = v11; }
            }
        }
    }
}

// LayerNorm over 128 elems; lane owns 4 CONSECUTIVE elems; writes split format.
__device__ __forceinline__ void ln_split(const float* __restrict__ src, unsigned* __restrict__ dst,
                                         const float* __restrict__ g, const float* __restrict__ b)
{
    const int lane = threadIdx.x & 31;
    float4 v = *(const float4*)(src + lane * 4);
    float s  = v.x + v.y + v.z + v.w;
    float sq = v.x*v.x + v.y*v.y + v.z*v.z + v.w*v.w;
    #pragma unroll
    for (int o = 16; o > 0; o >>= 1) {
        s  += __shfl_xor_sync(0xffffffffu, s,  o);
        sq += __shfl_xor_sync(0xffffffffu, sq, o);
    }
    float mean = s * (1.f/128.f);
    float rstd = rsqrtf(sq * (1.f/128.f) - mean*mean + 1e-5f);
    float4 gg = *(const float4*)(g + lane * 4);
    float4 bb = *(const float4*)(b + lane * 4);
    float y0 = (v.x-mean)*rstd*gg.x + bb.x;
    float y1 = (v.y-mean)*rstd*gg.y + bb.y;
    float y2 = (v.z-mean)*rstd*gg.z + bb.z;
    float y3 = (v.w-mean)*rstd*gg.w + bb.w;
    const int w  = lane >> 2;
    const int p0 = (lane & 3) * 2;
    store_split_pair(dst, w, p0,     y0, y1);
    store_split_pair(dst, w, p0 + 1, y2, y3);
}

__global__ void __launch_bounds__(NT, 1) fused_reasoner(
    const float* __restrict__ x,
    const float* __restrict__ bp,
    const float* __restrict__ ln1_g, const float* __restrict__ ln1_b,
    const float* __restrict__ bq, const float* __restrict__ bk,
    const float* __restrict__ bv, const float* __restrict__ bo,
    const float* __restrict__ bu,
    const float* __restrict__ ln2_g, const float* __restrict__ ln2_b,
    const float* __restrict__ bf1, const float* __restrict__ bf2,
    const float* __restrict__ ba, const float* __restrict__ bout,
    float* __restrict__ out)
{
    extern __shared__ unsigned SU[];
    float* Sf = (float*)SU;
    const int t = threadIdx.x;
    const int wid = t >> 5;            // 0..15
    const int row0 = blockIdx.x * ROWS;

    // ---- stage x tile (8 rows x 256) directly into split format at SP2 (stride 272) ----
    for (int idx = t; idx < 1024; idx += NT) {          // 8*128 pairs
        int nr = idx >> 7, pr = idx & 127;
        float2 xv = *(const float2*)(x + (size_t)(row0 + nr) * 256 + 2 * pr);
        store_split_pair(SU + OFF_SP2 + nr * 272, pr >> 3, pr & 7, xv.x, xv.y);
    }
    __syncthreads();
    // h = x @ Wp + bp (fp32 H; col j -> node j/128 col j%128)
    mma_gemm<8,256,1024,0,8,EPI_STORE,false, (1<<28),0, 128,LDH>(
        SU+OFF_SP2,272, nullptr,0, g_packed+PK_WP, bp, Sf+OFF_H, 8*LDH, 0);
    __syncthreads();

    #pragma unroll 1
    for (int l = 0; l < 3; l++) {
        const uint4* pkl = g_packed + PK_L0 + (long)l * PK_LSTR;
        const float* g1 = ln1_g + l*128;   const float* b1 = ln1_b + l*128;
        const float* g2 = ln2_g + l*128;   const float* b2 = ln2_b + l*128;

        // ---- LN1 -> hn split (SP1, stride 144) ----
        #pragma unroll
        for (int it = 0; it < 4; it++) {
            int p = it * 16 + wid;
            ln_split(Sf + OFF_H + p*LDH, SU + OFF_SP1 + p*144, g1, b1);
        }
        __syncthreads();

        // ---- Q,K,V projections (fp32 outs for scalar attention) ----
        mma_gemm<64,128,128,0,64,EPI_STORE,false>(SU+OFF_SP1,144, nullptr,0, pkl+PK_WQ, bq+l*128, Sf+OFF_QA, LDH, 0);
        mma_gemm<64,128,128,0,64,EPI_STORE,false>(SU+OFF_SP1,144, nullptr,0, pkl+PK_WK, bk+l*128, Sf+OFF_FK, LDH, 0);
        mma_gemm<64,128,128,0,64,EPI_STORE,false>(SU+OFF_SP1,144, nullptr,0, pkl+PK_WV, bv+l*128, Sf+OFF_FV, LDH, 0);
        __syncthreads();

        // ---- causal attention; att written in SPLIT form over Q region (stride 144) ----
        float pr8[8]; float inv = 0.f;
        int ar, ahd, an;
        if (t < 256) {
            ar = t >> 5; ahd = (t >> 3) & 3; an = t & 7;
            const float* qp = Sf + OFF_QA + (ar*8 + an)*LDH + ahd*32;
            float mx = -1e30f;
            #pragma unroll
            for (int m = 0; m < 8; m++) {
                if (m <= an) {
                    const float* kp = Sf + OFF_FK + (ar*8 + m)*LDH + ahd*32;
                    float sc = 0.f;
                    #pragma unroll
                    for (int d = 0; d < 32; d++) sc += qp[d] * kp[d];
                    sc *= 0.17677669529663688f;
                    pr8[m] = sc;
                    mx = fmaxf(mx, sc);
                }
            }
            float sum = 0.f;
            #pragma unroll
            for (int m = 0; m < 8; m++) if (m <= an) { pr8[m] = __expf(pr8[m] - mx); sum += pr8[m]; }
            inv = 1.f / sum;
        }
        __syncthreads();   // all Q reads done before split overwrite
        if (t < 256) {
            float o[32];
            #pragma unroll
            for (int d = 0; d < 32; d++) {
                float acc = 0.f;
                #pragma unroll
                for (int m = 0; m < 8; m++)
                    if (m <= an) acc += pr8[m] * (Sf + OFF_FV)[(ar*8 + m)*LDH + ahd*32 + d];
                o[d] = acc * inv;
            }
            unsigned* ad = SU + OFF_QA + (ar*8 + an)*144 + ahd*32;
            #pragma unroll
            for (int i = 0; i < 16; i++)
                store_split_pair(ad, i >> 3, i & 7, o[2*i], o[2*i+1]);
        }
        __syncthreads();

        // ---- attO = att @ Wo + bo -> split (SP2, 144) ----
        mma_gemm<64,128,128,0,64,EPI_STORE,true>(SU+OFF_QA,144, nullptr,0, pkl+PK_WO, bo+l*128, SU+OFF_SP2, 144, 0);
        __syncthreads();

        // ---- h += relu( [hn | attO] @ Wu + bu )  (fp32 H) ----
        mma_gemm<64,128,128,128,64,EPI_RELU_ADD,false>(SU+OFF_SP1,144, SU+OFF_SP2,144, pkl+PK_WU, bu+l*128, Sf+OFF_H, LDH, 0);
        __syncthreads();

        // ---- FFN in 2 chunks of 4 nodes; mid split 32x528 overlays FK+FV ----
        #pragma unroll 1
        for (int c = 0; c < 2; c++) {
            #pragma unroll
            for (int it = 0; it < 2; it++) {
                int p = it * 16 + wid;            // 0..31 = (r*4 + nn)
                int r = p >> 2, nn = p & 3;
                ln_split(Sf + OFF_H + (r*8 + c*4 + nn)*LDH, SU + OFF_QA + p*144, g2, b2);
            }
            __syncthreads();
            mma_gemm<32,128,512,0,32,EPI_GELU,true>(SU+OFF_QA,144, nullptr,0, pkl+PK_WF1, bf1+l*512, SU+OFF_FK, 528, 0);
            __syncthreads();
            mma_gemm<32,512,128,0,4,EPI_ADD,false>(SU+OFF_FK,528, nullptr,0, pkl+PK_WF2, bf2+l*128,
                                                   Sf+OFF_H + c*4*LDH, LDH, 8*LDH);
            __syncthreads();
        }
    }

    // ---- convert H -> splitH (SP1: batch stride 1168, node stride 144) ----
    for (int idx = t; idx < 4096; idx += NT) {          // 64 rows x 64 pairs
        int nr = idx >> 6, pr = idx & 63;
        float2 hv = *(const float2*)(Sf + OFF_H + nr*LDH + 2*pr);
        store_split_pair(SU + OFF_SP1 + (nr >> 3) * 1168 + (nr & 7) * 144, pr >> 3, pr & 7, hv.x, hv.y);
    }
    __syncthreads();
    // agg = gelu(flat @ Wa + ba) -> split (SP2, 144)
    mma_gemm<8,1024,128,0,8,EPI_GELU,true, 8,144>(SU+OFF_SP1,1168, nullptr,0, g_packed+PK_WA, ba, SU+OFF_SP2, 144, 0);
    __syncthreads();
    // out = agg @ Wout + bout (global fp32)
    mma_gemm<8,128,128,0,8,EPI_STORE,false>(SU+OFF_SP2,144, nullptr,0, g_packed+PK_WOUT, bout,
                                            out + (size_t)row0*128, 128, 0);
}

extern "C" void kernel_launch(void* const* d_in, const int* in_sizes, int n_in,
                              void* d_out, int out_size)
{
    (void)n_in; (void)out_size;
    const float* x     = (const float*)d_in[0];
    const float* Wp    = (const float*)d_in[1];
    const float* bp    = (const float*)d_in[2];
    const float* ln1_g = (const float*)d_in[3];
    const float* ln1_b = (const float*)d_in[4];
    const float* Wq    = (const float*)d_in[5];
    const float* bq    = (const float*)d_in[6];
    const float* Wk    = (const float*)d_in[7];
    const float* bk    = (const float*)d_in[8];
    const float* Wv    = (const float*)d_in[9];
    const float* bv    = (const float*)d_in[10];
    const float* Wo    = (const float*)d_in[11];
    const float* bo    = (const float*)d_in[12];
    const float* Wu    = (const float*)d_in[13];
    const float* bu    = (const float*)d_in[14];
    const float* ln2_g = (const float*)d_in[15];
    const float* ln2_b = (const float*)d_in[16];
    const float* Wf1   = (const float*)d_in[17];
    const float* bf1   = (const float*)d_in[18];
    const float* Wf2   = (const float*)d_in[19];
    const float* bf2   = (const float*)d_in[20];
    const float* Wa    = (const float*)d_in[21];
    const float* ba    = (const float*)d_in[22];
    const float* Wout  = (const float*)d_in[23];
    const float* bout  = (const float*)d_in[24];

    const int Bsz = in_sizes[0] / 256;       // DIN = 256
    const int grid = Bsz / ROWS;
    const size_t smem = SMEM_U32 * sizeof(unsigned);

    pack_weights<<<1072, 256>>>(Wp, Wq, Wk, Wv, Wo, Wu, Wf1, Wf2, Wa, Wout);

    cudaFuncSetAttribute(fused_reasoner, cudaFuncAttributeMaxDynamicSharedMemorySize, (int)smem);
    fused_reasoner<<<grid, NT, smem>>>(
        x, bp, ln1_g, ln1_b, bq, bk, bv, bo, bu, ln2_g, ln2_b,
        bf1, bf2, ba, bout, (float*)d_out);
}